// round 1
// baseline (speedup 1.0000x reference)
#include <cuda_runtime.h>
#include <cuda_bf16.h>
#include <math.h>

// Problem constants
#define NGRAPH 4096
#define NNODES 113
#define HID    128
#define PDIM   512
#define EMB    1024
#define EPS    1e-5f

// Scratch (no cudaMalloc allowed)
__device__ float g_z[NGRAPH * HID];        // pooled per-graph features
__device__ float g_p[NGRAPH * PDIM];       // projection pre-BN
__device__ float g_mean[PDIM];
__device__ float g_rstd[PDIM];

// ---------------------------------------------------------------------------
// Kernel 1: per-graph node pipeline + max pool.
// grid = NGRAPH blocks, 256 threads.
// dyn smem: W2s[128*128] | Hs[128*128] | red[16*128]
// ---------------------------------------------------------------------------
__global__ __launch_bounds__(256, 1)
void k_nodes(const float* __restrict__ x,
             const float* __restrict__ scaler,
             const float* __restrict__ W1,
             const float* __restrict__ b1,
             const float* __restrict__ gn_g,
             const float* __restrict__ gn_b,
             const float* __restrict__ W2,
             const float* __restrict__ b2)
{
    extern __shared__ float sm[];
    float* W2s = sm;                 // 16384 floats
    float* Hs  = sm + 16384;         // 16384 floats
    float* red = sm + 32768;         // 2048 floats

    __shared__ float W1s[3 * 128];
    __shared__ float b1s[128], gs[128], bsh[128], b2s[128];

    const int tid = threadIdx.x;
    const int g   = blockIdx.x;

    // ---- stage weights into smem ----
    {
        const float4* W2v  = (const float4*)W2;
        float4*       W2sv = (float4*)W2s;
        #pragma unroll 4
        for (int i = tid; i < 4096; i += 256) W2sv[i] = W2v[i];
        for (int i = tid; i < 384; i += 256)  W1s[i] = W1[i];
        if (tid < 128) {
            b1s[tid] = b1[tid];
            gs[tid]  = gn_g[tid];
            bsh[tid] = gn_b[tid];
            b2s[tid] = b2[tid];
        }
    }
    __syncthreads();

    // ---- phase 1a: h1 = (x*scaler) @ W1 + b1  -> Hs (pad rows 113..127 = 0)
    {
        const int c    = tid & 127;
        const int half = tid >> 7;
        const float* xg = x + (size_t)g * NNODES * 3;
        for (int n = half; n < 128; n += 2) {
            float v = 0.f;
            if (n < NNODES) {
                float a0 = xg[n * 3 + 0] * scaler[n * 3 + 0];
                float a1 = xg[n * 3 + 1] * scaler[n * 3 + 1];
                float a2 = xg[n * 3 + 2] * scaler[n * 3 + 2];
                v = fmaf(a0, W1s[c],
                    fmaf(a1, W1s[128 + c],
                    fmaf(a2, W1s[256 + c], b1s[c])));
            }
            Hs[n * 128 + c] = v;
        }
    }
    __syncthreads();

    // ---- phase 1b: GroupNorm(8 groups of 16) + LeakyReLU(0.2), in place
    for (int gi = tid; gi < NNODES * 8; gi += 256) {
        const int n   = gi >> 3;
        const int grp = gi & 7;
        float* hp = Hs + n * 128 + grp * 16;
        float s = 0.f, ss = 0.f;
        #pragma unroll
        for (int j = 0; j < 16; j++) { float v = hp[j]; s += v; ss += v * v; }
        const float mu  = s * 0.0625f;
        const float var = ss * 0.0625f - mu * mu;
        const float inv = rsqrtf(var + EPS);
        #pragma unroll
        for (int j = 0; j < 16; j++) {
            const int cc = grp * 16 + j;
            float v = (hp[j] - mu) * inv * gs[cc] + bsh[cc];
            hp[j] = v > 0.f ? v : 0.2f * v;
        }
    }
    __syncthreads();

    // ---- phase 2: H(128x128) @ W2(128x128), 8x8 register tile, fused max
    const int tx = tid & 15;          // column group
    const int ty = tid >> 4;          // row group
    const int r0 = ty * 8;

    float acc[8][8];
    #pragma unroll
    for (int i = 0; i < 8; i++)
        #pragma unroll
        for (int j = 0; j < 8; j++) acc[i][j] = 0.f;

    #pragma unroll 2
    for (int k = 0; k < 128; k++) {
        float a[8], b[8];
        #pragma unroll
        for (int i = 0; i < 8; i++) a[i] = Hs[(r0 + i) * 128 + k];
        #pragma unroll
        for (int j = 0; j < 8; j++) b[j] = W2s[k * 128 + tx + 16 * j];
        #pragma unroll
        for (int i = 0; i < 8; i++)
            #pragma unroll
            for (int j = 0; j < 8; j++)
                acc[i][j] = fmaf(a[i], b[j], acc[i][j]);
    }

    // per-thread max over valid rows
    float m[8];
    #pragma unroll
    for (int j = 0; j < 8; j++) m[j] = -3.402823466e+38f;
    #pragma unroll
    for (int i = 0; i < 8; i++) {
        if (r0 + i < NNODES) {
            #pragma unroll
            for (int j = 0; j < 8; j++) m[j] = fmaxf(m[j], acc[i][j]);
        }
    }
    #pragma unroll
    for (int j = 0; j < 8; j++) red[ty * 128 + tx + 16 * j] = m[j];
    __syncthreads();

    if (tid < 128) {
        float zz = red[tid];
        #pragma unroll
        for (int t = 1; t < 16; t++) zz = fmaxf(zz, red[t * 128 + tid]);
        g_z[(size_t)g * 128 + tid] = zz + b2s[tid];
    }
}

// ---------------------------------------------------------------------------
// Kernel 2: p = z @ W3 + b3.  grid (64, 4): 64-row x 128-col tiles. 256 thr.
// dyn smem: zs[64*128] | w3s[128*128]
// ---------------------------------------------------------------------------
__global__ __launch_bounds__(256, 1)
void k_proj(const float* __restrict__ W3, const float* __restrict__ b3)
{
    extern __shared__ float sm[];
    float* zs  = sm;            // 8192
    float* w3s = sm + 8192;     // 16384

    const int tid  = threadIdx.x;
    const int row0 = blockIdx.x * 64;
    const int col0 = blockIdx.y * 128;

    // load z tile (64x128) and W3 tile (128x128)
    {
        const float4* zv  = (const float4*)(g_z + (size_t)row0 * 128);
        float4*       zsv = (float4*)zs;
        #pragma unroll
        for (int i = tid; i < 2048; i += 256) zsv[i] = zv[i];

        const float4* W3v  = (const float4*)W3;
        float4*       w3sv = (float4*)w3s;
        #pragma unroll
        for (int i = tid; i < 4096; i += 256) {
            const int k = i >> 5, q = i & 31;
            w3sv[i] = W3v[k * 128 + (col0 >> 2) + q];
        }
    }
    __syncthreads();

    const int tx = tid & 31;
    const int ty = tid >> 5;   // 0..7

    float acc[8][4];
    #pragma unroll
    for (int i = 0; i < 8; i++)
        #pragma unroll
        for (int j = 0; j < 4; j++) acc[i][j] = 0.f;

    #pragma unroll 2
    for (int k = 0; k < 128; k++) {
        float a[8], b[4];
        #pragma unroll
        for (int i = 0; i < 8; i++) a[i] = zs[(ty + 8 * i) * 128 + k];
        #pragma unroll
        for (int j = 0; j < 4; j++) b[j] = w3s[k * 128 + tx + 32 * j];
        #pragma unroll
        for (int i = 0; i < 8; i++)
            #pragma unroll
            for (int j = 0; j < 4; j++)
                acc[i][j] = fmaf(a[i], b[j], acc[i][j]);
    }

    #pragma unroll
    for (int i = 0; i < 8; i++) {
        const int r = row0 + ty + 8 * i;
        #pragma unroll
        for (int j = 0; j < 4; j++) {
            const int c = col0 + tx + 32 * j;
            g_p[(size_t)r * PDIM + c] = acc[i][j] + b3[c];
        }
    }
}

// ---------------------------------------------------------------------------
// Kernel 3: per-channel batch stats. grid 4, 128 threads. c = bx*128+tid.
// ---------------------------------------------------------------------------
__global__ void k_stats()
{
    const int c = blockIdx.x * 128 + threadIdx.x;
    float s0 = 0.f, s1 = 0.f, s2 = 0.f, s3 = 0.f;
    float q0 = 0.f, q1 = 0.f, q2 = 0.f, q3 = 0.f;
    const float* pc = g_p + c;
    for (int r = 0; r < NGRAPH; r += 4) {
        float v0 = pc[(size_t)(r + 0) * PDIM];
        float v1 = pc[(size_t)(r + 1) * PDIM];
        float v2 = pc[(size_t)(r + 2) * PDIM];
        float v3 = pc[(size_t)(r + 3) * PDIM];
        s0 += v0; q0 = fmaf(v0, v0, q0);
        s1 += v1; q1 = fmaf(v1, v1, q1);
        s2 += v2; q2 = fmaf(v2, v2, q2);
        s3 += v3; q3 = fmaf(v3, v3, q3);
    }
    const float s = (s0 + s1) + (s2 + s3);
    const float q = (q0 + q1) + (q2 + q3);
    const float mean = s * (1.f / NGRAPH);
    const float var  = q * (1.f / NGRAPH) - mean * mean;
    g_mean[c] = mean;
    g_rstd[c] = rsqrtf(var + EPS);
}

// ---------------------------------------------------------------------------
// Kernel 4: out = L2norm( relu(BN(p)) @ W4 + b4 ).
// grid 256 blocks (16 graph rows each), 256 threads (4 cols each, all 16 rows)
// ---------------------------------------------------------------------------
__global__ __launch_bounds__(256, 1)
void k_out(const float* __restrict__ bn_g, const float* __restrict__ bn_b,
           const float* __restrict__ W4,   const float* __restrict__ b4,
           float* __restrict__ out)
{
    __shared__ float ts[16 * PDIM];   // 32 KB; reused as reduction buffer later
    __shared__ float inv[16];

    const int tid  = threadIdx.x;
    const int row0 = blockIdx.x * 16;

    // BN + ReLU into smem
    #pragma unroll
    for (int it = 0; it < 32; it++) {
        const int i = tid + 256 * it;
        const int r = i >> 9, c = i & 511;
        float v = g_p[(size_t)(row0 + r) * PDIM + c];
        v = (v - g_mean[c]) * g_rstd[c] * bn_g[c] + bn_b[c];
        ts[i] = v > 0.f ? v : 0.f;
    }
    __syncthreads();

    const int c0 = tid * 4;
    float acc[16][4];
    #pragma unroll
    for (int r = 0; r < 16; r++)
        #pragma unroll
        for (int j = 0; j < 4; j++) acc[r][j] = 0.f;

    const float4* W4v = (const float4*)W4;
    #pragma unroll 2
    for (int k = 0; k < PDIM; k++) {
        const float4 w = __ldg(&W4v[(size_t)k * 256 + tid]);
        #pragma unroll
        for (int r = 0; r < 16; r++) {
            const float a = ts[r * PDIM + k];
            acc[r][0] = fmaf(a, w.x, acc[r][0]);
            acc[r][1] = fmaf(a, w.y, acc[r][1]);
            acc[r][2] = fmaf(a, w.z, acc[r][2]);
            acc[r][3] = fmaf(a, w.w, acc[r][3]);
        }
    }

    const float4 bb = __ldg(&((const float4*)b4)[tid]);
    #pragma unroll
    for (int r = 0; r < 16; r++) {
        acc[r][0] += bb.x; acc[r][1] += bb.y;
        acc[r][2] += bb.z; acc[r][3] += bb.w;
    }

    __syncthreads();                   // all ts reads done; reuse as scratch
    float* part = ts;                  // [16][256]
    #pragma unroll
    for (int r = 0; r < 16; r++) {
        float s = acc[r][0] * acc[r][0] + acc[r][1] * acc[r][1]
                + acc[r][2] * acc[r][2] + acc[r][3] * acc[r][3];
        part[r * 256 + tid] = s;
    }
    __syncthreads();
    if (tid < 16) {
        float s = 0.f;
        #pragma unroll 8
        for (int t = 0; t < 256; t++) s += part[tid * 256 + t];
        const float nrm = sqrtf(s);
        inv[tid] = 1.f / fmaxf(nrm, 1e-12f);
    }
    __syncthreads();

    float4* ov = (float4*)out;
    #pragma unroll
    for (int r = 0; r < 16; r++) {
        const float iv = inv[r];
        float4 o;
        o.x = acc[r][0] * iv; o.y = acc[r][1] * iv;
        o.z = acc[r][2] * iv; o.w = acc[r][3] * iv;
        ov[(size_t)(row0 + r) * 256 + tid] = o;
    }
}

// ---------------------------------------------------------------------------
extern "C" void kernel_launch(void* const* d_in, const int* in_sizes, int n_in,
                              void* d_out, int out_size)
{
    const float* x      = (const float*)d_in[0];
    const float* scaler = (const float*)d_in[1];
    const float* W1     = (const float*)d_in[2];
    const float* b1     = (const float*)d_in[3];
    const float* gn_g   = (const float*)d_in[4];
    const float* gn_b   = (const float*)d_in[5];
    const float* W2     = (const float*)d_in[6];
    const float* b2     = (const float*)d_in[7];
    const float* W3     = (const float*)d_in[8];
    const float* b3     = (const float*)d_in[9];
    const float* bn_g   = (const float*)d_in[10];
    const float* bn_b   = (const float*)d_in[11];
    const float* W4     = (const float*)d_in[12];
    const float* b4     = (const float*)d_in[13];
    // d_in[14] = batch (implicit: contiguous 113-node segments)
    float* out = (float*)d_out;

    const int smem1 = (16384 + 16384 + 2048) * 4;   // 139264
    const int smem2 = (8192 + 16384) * 4;           // 98304
    cudaFuncSetAttribute(k_nodes, cudaFuncAttributeMaxDynamicSharedMemorySize, smem1);
    cudaFuncSetAttribute(k_proj,  cudaFuncAttributeMaxDynamicSharedMemorySize, smem2);

    k_nodes<<<NGRAPH, 256, smem1>>>(x, scaler, W1, b1, gn_g, gn_b, W2, b2);
    k_proj<<<dim3(64, 4), 256, smem2>>>(W3, b3);
    k_stats<<<4, 128>>>();
    k_out<<<256, 256>>>(bn_g, bn_b, W4, b4, out);
}

// round 3
// speedup vs baseline: 2.0380x; 2.0380x over previous
#include <cuda_runtime.h>
#include <cuda_bf16.h>
#include <math.h>
#include <cstdint>

#define NGRAPH 4096
#define NNODES 113
#define HID    128
#define PDIM   512
#define EMB    1024
#define EPS    1e-5f
#define NEGINF -3.402823466e+38f
#define WSTRIDE 136   // padded bf16 row stride for smem tiles

// ---------------------------------------------------------------------------
// Scratch (no cudaMalloc allowed)
// ---------------------------------------------------------------------------
__device__ float g_z[NGRAPH * HID];
__device__ float g_p[NGRAPH * PDIM];
__device__ float g_mean[PDIM];
__device__ float g_rstd[PDIM];
// W2^T split to bf16 hi/lo, [n][k] with padded stride 136
__device__ __align__(16) __nv_bfloat16 g_w2hi[128 * WSTRIDE];
__device__ __align__(16) __nv_bfloat16 g_w2lo[128 * WSTRIDE];

// ---------------------------------------------------------------------------
// mma.sync helpers (arch-agnostic tensor path; works on plain sm_103 target)
// ---------------------------------------------------------------------------
__device__ __forceinline__ uint32_t smem_u32(const void* p) {
    uint32_t a;
    asm("{ .reg .u64 t; cvta.to.shared.u64 t, %1; cvt.u32.u64 %0, t; }"
        : "=r"(a) : "l"(p));
    return a;
}
__device__ __forceinline__ void ldsm_x4(uint32_t* r, uint32_t addr) {
    asm volatile("ldmatrix.sync.aligned.m8n8.x4.shared.b16 {%0,%1,%2,%3}, [%4];"
        : "=r"(r[0]), "=r"(r[1]), "=r"(r[2]), "=r"(r[3]) : "r"(addr));
}
__device__ __forceinline__ void ldsm_x2(uint32_t* r, uint32_t addr) {
    asm volatile("ldmatrix.sync.aligned.m8n8.x2.shared.b16 {%0,%1}, [%2];"
        : "=r"(r[0]), "=r"(r[1]) : "r"(addr));
}
__device__ __forceinline__ void mma16816(float* d, const uint32_t* a, const uint32_t* b) {
    asm volatile(
        "mma.sync.aligned.m16n8k16.row.col.f32.bf16.bf16.f32 "
        "{%0,%1,%2,%3}, {%4,%5,%6,%7}, {%8,%9}, {%0,%1,%2,%3};"
        : "+f"(d[0]), "+f"(d[1]), "+f"(d[2]), "+f"(d[3])
        : "r"(a[0]), "r"(a[1]), "r"(a[2]), "r"(a[3]), "r"(b[0]), "r"(b[1]));
}

// ---------------------------------------------------------------------------
// Prep: W2 [K=128, N=128] -> W2^T [N, K] bf16 hi/lo, padded stride.
// ---------------------------------------------------------------------------
__global__ void k_prep(const float* __restrict__ W2)
{
    const int idx = blockIdx.x * blockDim.x + threadIdx.x;
    if (idx >= 16384) return;
    const int n = idx >> 7, k = idx & 127;
    const float v = W2[k * 128 + n];
    const __nv_bfloat16 hi = __float2bfloat16(v);
    const __nv_bfloat16 lo = __float2bfloat16(v - __bfloat162float(hi));
    g_w2hi[n * WSTRIDE + k] = hi;
    g_w2lo[n * WSTRIDE + k] = lo;
}

// ---------------------------------------------------------------------------
// Kernel 1: per-graph node pipeline + HMMA GEMM + fused max pool.
// grid = NGRAPH, 256 threads (8 warps). dyn smem: Hhi|Hlo|Whi|Wlo (4x34816B)
// ---------------------------------------------------------------------------
__global__ __launch_bounds__(256, 1)
void k_nodes(const float* __restrict__ x,
             const float* __restrict__ scaler,
             const float* __restrict__ W1,
             const float* __restrict__ b1,
             const float* __restrict__ gn_g,
             const float* __restrict__ gn_b,
             const float* __restrict__ b2)
{
    extern __shared__ __align__(16) char sm[];
    __nv_bfloat16* Hhi = (__nv_bfloat16*)sm;                      // 128*136
    __nv_bfloat16* Hlo = (__nv_bfloat16*)(sm + 34816);
    __nv_bfloat16* Whi = (__nv_bfloat16*)(sm + 2 * 34816);
    __nv_bfloat16* Wlo = (__nv_bfloat16*)(sm + 3 * 34816);

    __shared__ float W1s[384], b1s[128], gs[128], bsh[128], b2s[128];
    __shared__ float red[8 * 128];

    const int tid  = threadIdx.x, g = blockIdx.x;
    const int wid  = tid >> 5, lane = tid & 31;

    // stage small params
    for (int i = tid; i < 384; i += 256) W1s[i] = W1[i];
    if (tid < 128) {
        b1s[tid] = b1[tid]; gs[tid] = gn_g[tid];
        bsh[tid] = gn_b[tid]; b2s[tid] = b2[tid];
    }
    // stage pre-split W2^T hi/lo (linear copy, padded layout preserved)
    {
        const uint4* sh = (const uint4*)g_w2hi;
        const uint4* sl = (const uint4*)g_w2lo;
        uint4* dh = (uint4*)Whi;
        uint4* dl = (uint4*)Wlo;
        #pragma unroll
        for (int i = tid; i < 2176; i += 256) { dh[i] = sh[i]; dl[i] = sl[i]; }
    }
    __syncthreads();

    // ---- H = LeakyReLU(GN(x*scaler @ W1 + b1)) -> bf16 hi/lo smem tiles
    const float* xg = x + (size_t)g * NNODES * 3;
    #pragma unroll
    for (int it = 0; it < 4; it++) {
        const int pair = tid + 256 * it;
        if (pair < NNODES * 8) {
            const int n = pair >> 3, grp = pair & 7;
            const float a0 = xg[n * 3 + 0] * scaler[n * 3 + 0];
            const float a1 = xg[n * 3 + 1] * scaler[n * 3 + 1];
            const float a2 = xg[n * 3 + 2] * scaler[n * 3 + 2];
            float v[16], s = 0.f, ss = 0.f;
            #pragma unroll
            for (int j = 0; j < 16; j++) {
                const int c = grp * 16 + j;
                float h = fmaf(a0, W1s[c],
                          fmaf(a1, W1s[128 + c],
                          fmaf(a2, W1s[256 + c], b1s[c])));
                v[j] = h; s += h; ss += h * h;
            }
            const float mu  = s * 0.0625f;
            const float var = ss * 0.0625f - mu * mu;
            const float inv = rsqrtf(var + EPS);
            const int base = n * WSTRIDE + grp * 16;
            #pragma unroll
            for (int j2 = 0; j2 < 8; j2++) {
                float h0 = (v[2 * j2] - mu) * inv * gs[grp * 16 + 2 * j2] + bsh[grp * 16 + 2 * j2];
                float h1 = (v[2 * j2 + 1] - mu) * inv * gs[grp * 16 + 2 * j2 + 1] + bsh[grp * 16 + 2 * j2 + 1];
                h0 = h0 > 0.f ? h0 : 0.2f * h0;
                h1 = h1 > 0.f ? h1 : 0.2f * h1;
                const __nv_bfloat16 hi0 = __float2bfloat16(h0);
                const __nv_bfloat16 hi1 = __float2bfloat16(h1);
                const __nv_bfloat16 lo0 = __float2bfloat16(h0 - __bfloat162float(hi0));
                const __nv_bfloat16 lo1 = __float2bfloat16(h1 - __bfloat162float(hi1));
                __nv_bfloat162 ph; ph.x = hi0; ph.y = hi1;
                __nv_bfloat162 pl; pl.x = lo0; pl.y = lo1;
                *(__nv_bfloat162*)(Hhi + base + 2 * j2) = ph;
                *(__nv_bfloat162*)(Hlo + base + 2 * j2) = pl;
            }
        } else if (pair < 128 * 8) {
            // zero pad rows 113..127 (keeps accumulators finite)
            const int n = pair >> 3, grp = pair & 7;
            const int base = n * WSTRIDE + grp * 16;
            #pragma unroll
            for (int j2 = 0; j2 < 8; j2++) {
                *(uint32_t*)(Hhi + base + 2 * j2) = 0u;
                *(uint32_t*)(Hlo + base + 2 * j2) = 0u;
            }
        }
    }
    __syncthreads();

    // ---- HMMA: warp w computes rows 16w..16w+15 x all 128 cols
    const uint32_t Hhi_b = smem_u32(Hhi);
    const uint32_t Hlo_b = smem_u32(Hlo);
    const uint32_t Whi_b = smem_u32(Whi);
    const uint32_t Wlo_b = smem_u32(Wlo);

    const int seg = lane >> 3, ris = lane & 7;
    const uint32_t a_off = (uint32_t)(((16 * wid + (seg & 1) * 8 + ris) * WSTRIDE
                                       + (seg >> 1) * 8) * 2);
    const uint32_t b_rel = (uint32_t)((ris * WSTRIDE + (seg & 1) * 8) * 2);

    float acc[16][4];
    #pragma unroll
    for (int j = 0; j < 16; j++)
        #pragma unroll
        for (int q = 0; q < 4; q++) acc[j][q] = 0.f;

    #pragma unroll
    for (int kt = 0; kt < 8; kt++) {
        const int k0 = kt * 16;
        uint32_t ah[4], al[4];
        ldsm_x4(ah, Hhi_b + a_off + k0 * 2);
        ldsm_x4(al, Hlo_b + a_off + k0 * 2);
        #pragma unroll
        for (int j = 0; j < 16; j++) {
            const uint32_t boff = b_rel + (uint32_t)((j * 8 * WSTRIDE + k0) * 2);
            uint32_t bh[2], bl[2];
            ldsm_x2(bh, Whi_b + boff);
            ldsm_x2(bl, Wlo_b + boff);
            mma16816(acc[j], ah, bh);
            mma16816(acc[j], al, bh);
            mma16816(acc[j], ah, bl);
        }
    }

    // ---- fused max pool: rows of warp strip, then cross-warp via smem
    const int rbase = 16 * wid + (lane >> 2);
    const bool v0 = rbase < NNODES;
    const bool v1 = (rbase + 8) < NNODES;
    #pragma unroll
    for (int j = 0; j < 16; j++) {
        float m0 = fmaxf(v0 ? acc[j][0] : NEGINF, v1 ? acc[j][2] : NEGINF);
        float m1 = fmaxf(v0 ? acc[j][1] : NEGINF, v1 ? acc[j][3] : NEGINF);
        #pragma unroll
        for (int sh = 4; sh < 32; sh <<= 1) {
            m0 = fmaxf(m0, __shfl_xor_sync(0xffffffffu, m0, sh));
            m1 = fmaxf(m1, __shfl_xor_sync(0xffffffffu, m1, sh));
        }
        if (lane < 4) {
            red[wid * 128 + j * 8 + lane * 2]     = m0;
            red[wid * 128 + j * 8 + lane * 2 + 1] = m1;
        }
    }
    __syncthreads();
    if (tid < 128) {
        float m = red[tid];
        #pragma unroll
        for (int w2 = 1; w2 < 8; w2++) m = fmaxf(m, red[w2 * 128 + tid]);
        g_z[(size_t)g * 128 + tid] = m + b2s[tid];
    }
}

// ---------------------------------------------------------------------------
// Kernel 2: p = z @ W3 + b3.  grid (64, 4). 256 thr.
// ---------------------------------------------------------------------------
__global__ __launch_bounds__(256, 1)
void k_proj(const float* __restrict__ W3, const float* __restrict__ b3)
{
    extern __shared__ float smf[];
    float* zs  = smf;            // 8192
    float* w3s = smf + 8192;     // 16384

    const int tid  = threadIdx.x;
    const int row0 = blockIdx.x * 64;
    const int col0 = blockIdx.y * 128;

    {
        const float4* zv  = (const float4*)(g_z + (size_t)row0 * 128);
        float4*       zsv = (float4*)zs;
        #pragma unroll
        for (int i = tid; i < 2048; i += 256) zsv[i] = zv[i];

        const float4* W3v  = (const float4*)W3;
        float4*       w3sv = (float4*)w3s;
        #pragma unroll
        for (int i = tid; i < 4096; i += 256) {
            const int k = i >> 5, q = i & 31;
            w3sv[i] = W3v[k * 128 + (col0 >> 2) + q];
        }
    }
    __syncthreads();

    const int tx = tid & 31;
    const int ty = tid >> 5;

    float acc[8][4];
    #pragma unroll
    for (int i = 0; i < 8; i++)
        #pragma unroll
        for (int j = 0; j < 4; j++) acc[i][j] = 0.f;

    #pragma unroll 2
    for (int k = 0; k < 128; k++) {
        float a[8], b[4];
        #pragma unroll
        for (int i = 0; i < 8; i++) a[i] = zs[(ty + 8 * i) * 128 + k];
        #pragma unroll
        for (int j = 0; j < 4; j++) b[j] = w3s[k * 128 + tx + 32 * j];
        #pragma unroll
        for (int i = 0; i < 8; i++)
            #pragma unroll
            for (int j = 0; j < 4; j++)
                acc[i][j] = fmaf(a[i], b[j], acc[i][j]);
    }

    #pragma unroll
    for (int i = 0; i < 8; i++) {
        const int r = row0 + ty + 8 * i;
        #pragma unroll
        for (int j = 0; j < 4; j++) {
            const int c = col0 + tx + 32 * j;
            g_p[(size_t)r * PDIM + c] = acc[i][j] + b3[c];
        }
    }
}

// ---------------------------------------------------------------------------
// Kernel 3: per-channel batch stats.
// ---------------------------------------------------------------------------
__global__ void k_stats()
{
    const int c = blockIdx.x * 128 + threadIdx.x;
    float s0 = 0.f, s1 = 0.f, s2 = 0.f, s3 = 0.f;
    float q0 = 0.f, q1 = 0.f, q2 = 0.f, q3 = 0.f;
    const float* pc = g_p + c;
    for (int r = 0; r < NGRAPH; r += 4) {
        float v0 = pc[(size_t)(r + 0) * PDIM];
        float v1 = pc[(size_t)(r + 1) * PDIM];
        float v2 = pc[(size_t)(r + 2) * PDIM];
        float v3 = pc[(size_t)(r + 3) * PDIM];
        s0 += v0; q0 = fmaf(v0, v0, q0);
        s1 += v1; q1 = fmaf(v1, v1, q1);
        s2 += v2; q2 = fmaf(v2, v2, q2);
        s3 += v3; q3 = fmaf(v3, v3, q3);
    }
    const float s = (s0 + s1) + (s2 + s3);
    const float q = (q0 + q1) + (q2 + q3);
    const float mean = s * (1.f / NGRAPH);
    const float var  = q * (1.f / NGRAPH) - mean * mean;
    g_mean[c] = mean;
    g_rstd[c] = rsqrtf(var + EPS);
}

// ---------------------------------------------------------------------------
// Kernel 4: out = L2norm( relu(BN(p)) @ W4 + b4 ).
// grid 512 blocks (8 rows each) for better SM balance, 256 threads.
// ---------------------------------------------------------------------------
__global__ __launch_bounds__(256, 1)
void k_out(const float* __restrict__ bn_g, const float* __restrict__ bn_b,
           const float* __restrict__ W4,   const float* __restrict__ b4,
           float* __restrict__ out)
{
    __shared__ float ts[8 * PDIM];    // 16 KB
    __shared__ float inv[8];

    const int tid  = threadIdx.x;
    const int row0 = blockIdx.x * 8;

    #pragma unroll
    for (int it = 0; it < 16; it++) {
        const int i = tid + 256 * it;
        const int r = i >> 9, c = i & 511;
        float v = g_p[(size_t)(row0 + r) * PDIM + c];
        v = (v - g_mean[c]) * g_rstd[c] * bn_g[c] + bn_b[c];
        ts[i] = v > 0.f ? v : 0.f;
    }
    __syncthreads();

    float acc[8][4];
    #pragma unroll
    for (int r = 0; r < 8; r++)
        #pragma unroll
        for (int j = 0; j < 4; j++) acc[r][j] = 0.f;

    const float4* W4v = (const float4*)W4;
    #pragma unroll 2
    for (int k = 0; k < PDIM; k++) {
        const float4 w = __ldg(&W4v[(size_t)k * 256 + tid]);
        #pragma unroll
        for (int r = 0; r < 8; r++) {
            const float a = ts[r * PDIM + k];
            acc[r][0] = fmaf(a, w.x, acc[r][0]);
            acc[r][1] = fmaf(a, w.y, acc[r][1]);
            acc[r][2] = fmaf(a, w.z, acc[r][2]);
            acc[r][3] = fmaf(a, w.w, acc[r][3]);
        }
    }

    const float4 bb = __ldg(&((const float4*)b4)[tid]);
    #pragma unroll
    for (int r = 0; r < 8; r++) {
        acc[r][0] += bb.x; acc[r][1] += bb.y;
        acc[r][2] += bb.z; acc[r][3] += bb.w;
    }

    __syncthreads();
    float* part = ts;                 // reuse as [8][256]
    #pragma unroll
    for (int r = 0; r < 8; r++) {
        float s = acc[r][0] * acc[r][0] + acc[r][1] * acc[r][1]
                + acc[r][2] * acc[r][2] + acc[r][3] * acc[r][3];
        part[r * 256 + tid] = s;
    }
    __syncthreads();
    if (tid < 8) {
        float s = 0.f;
        #pragma unroll 8
        for (int t = 0; t < 256; t++) s += part[tid * 256 + t];
        inv[tid] = 1.f / fmaxf(sqrtf(s), 1e-12f);
    }
    __syncthreads();

    float4* ov = (float4*)out;
    #pragma unroll
    for (int r = 0; r < 8; r++) {
        const float iv = inv[r];
        float4 o;
        o.x = acc[r][0] * iv; o.y = acc[r][1] * iv;
        o.z = acc[r][2] * iv; o.w = acc[r][3] * iv;
        ov[(size_t)(row0 + r) * 256 + tid] = o;
    }
}

// ---------------------------------------------------------------------------
extern "C" void kernel_launch(void* const* d_in, const int* in_sizes, int n_in,
                              void* d_out, int out_size)
{
    const float* x      = (const float*)d_in[0];
    const float* scaler = (const float*)d_in[1];
    const float* W1     = (const float*)d_in[2];
    const float* b1     = (const float*)d_in[3];
    const float* gn_g   = (const float*)d_in[4];
    const float* gn_b   = (const float*)d_in[5];
    const float* W2     = (const float*)d_in[6];
    const float* b2     = (const float*)d_in[7];
    const float* W3     = (const float*)d_in[8];
    const float* b3     = (const float*)d_in[9];
    const float* bn_g   = (const float*)d_in[10];
    const float* bn_b   = (const float*)d_in[11];
    const float* W4     = (const float*)d_in[12];
    const float* b4     = (const float*)d_in[13];
    float* out = (float*)d_out;

    const int smem1 = 4 * 34816;             // 139264
    const int smem2 = (8192 + 16384) * 4;    // 98304
    cudaFuncSetAttribute(k_nodes, cudaFuncAttributeMaxDynamicSharedMemorySize, smem1);
    cudaFuncSetAttribute(k_proj,  cudaFuncAttributeMaxDynamicSharedMemorySize, smem2);

    k_prep<<<64, 256>>>(W2);
    k_nodes<<<NGRAPH, 256, smem1>>>(x, scaler, W1, b1, gn_g, gn_b, b2);
    k_proj<<<dim3(64, 4), 256, smem2>>>(W3, b3);
    k_stats<<<4, 128>>>();
    k_out<<<512, 256>>>(bn_g, bn_b, W4, b4, out);
}

// round 6
// speedup vs baseline: 3.0633x; 1.5031x over previous
#include <cuda_runtime.h>
#include <cuda_bf16.h>
#include <math.h>
#include <cstdint>

#define NGRAPH 4096
#define NNODES 113
#define HID    128
#define PDIM   512
#define EMB    1024
#define EPS    1e-5f
#define NEGINF -3.402823466e+38f
#define WSTRIDE 136   // padded bf16 row stride for k_nodes smem tiles
#define KSTR    520   // padded bf16 row stride for k_out A tiles

// ---------------------------------------------------------------------------
// Scratch (no cudaMalloc allowed)
// ---------------------------------------------------------------------------
__device__ float g_z[NGRAPH * HID];
__device__ float g_p[NGRAPH * PDIM];
__device__ float g_mean[PDIM];
__device__ float g_rstd[PDIM];
__device__ float g_psum[64 * PDIM];
__device__ float g_qsum[64 * PDIM];
// W2^T split to bf16 hi/lo, [n][k] padded stride 136
__device__ __align__(16) __nv_bfloat16 g_w2hi[128 * WSTRIDE];
__device__ __align__(16) __nv_bfloat16 g_w2lo[128 * WSTRIDE];
// W4^T split to bf16 hi/lo, [n=1024][k=512]
__device__ __align__(16) __nv_bfloat16 g_w4hi[EMB * PDIM];
__device__ __align__(16) __nv_bfloat16 g_w4lo[EMB * PDIM];

// ---------------------------------------------------------------------------
// mma.sync helpers (arch-agnostic tensor path; plain sm_103-safe)
// ---------------------------------------------------------------------------
__device__ __forceinline__ uint32_t smem_u32(const void* p) {
    uint32_t a;
    asm("{ .reg .u64 t; cvta.to.shared.u64 t, %1; cvt.u32.u64 %0, t; }"
        : "=r"(a) : "l"(p));
    return a;
}
__device__ __forceinline__ void ldsm_x4(uint32_t* r, uint32_t addr) {
    asm volatile("ldmatrix.sync.aligned.m8n8.x4.shared.b16 {%0,%1,%2,%3}, [%4];"
        : "=r"(r[0]), "=r"(r[1]), "=r"(r[2]), "=r"(r[3]) : "r"(addr));
}
__device__ __forceinline__ void ldsm_x2(uint32_t* r, uint32_t addr) {
    asm volatile("ldmatrix.sync.aligned.m8n8.x2.shared.b16 {%0,%1}, [%2];"
        : "=r"(r[0]), "=r"(r[1]) : "r"(addr));
}
__device__ __forceinline__ void mma16816(float* d, const uint32_t* a, const uint32_t* b) {
    asm volatile(
        "mma.sync.aligned.m16n8k16.row.col.f32.bf16.bf16.f32 "
        "{%0,%1,%2,%3}, {%4,%5,%6,%7}, {%8,%9}, {%0,%1,%2,%3};"
        : "+f"(d[0]), "+f"(d[1]), "+f"(d[2]), "+f"(d[3])
        : "r"(a[0]), "r"(a[1]), "r"(a[2]), "r"(a[3]), "r"(b[0]), "r"(b[1]));
}

// ---------------------------------------------------------------------------
// Prep kernels: split weights into bf16 hi/lo transposed layouts.
// ---------------------------------------------------------------------------
__global__ void k_prep(const float* __restrict__ W2)
{
    const int idx = blockIdx.x * blockDim.x + threadIdx.x;
    if (idx >= 16384) return;
    const int n = idx >> 7, k = idx & 127;
    const float v = W2[k * 128 + n];
    const __nv_bfloat16 hi = __float2bfloat16(v);
    g_w2hi[n * WSTRIDE + k] = hi;
    g_w2lo[n * WSTRIDE + k] = __float2bfloat16(v - __bfloat162float(hi));
}

__global__ void k_prep4(const float* __restrict__ W4)
{
    const int idx = blockIdx.x * blockDim.x + threadIdx.x;   // 524288
    const int n = idx >> 9, k = idx & 511;
    const float v = W4[(size_t)k * EMB + n];
    const __nv_bfloat16 hi = __float2bfloat16(v);
    g_w4hi[(size_t)n * PDIM + k] = hi;
    g_w4lo[(size_t)n * PDIM + k] = __float2bfloat16(v - __bfloat162float(hi));
}

// ---------------------------------------------------------------------------
// Kernel 1: per-graph node pipeline + HMMA GEMM + fused max pool.
// ---------------------------------------------------------------------------
__global__ __launch_bounds__(256, 1)
void k_nodes(const float* __restrict__ x,
             const float* __restrict__ scaler,
             const float* __restrict__ W1,
             const float* __restrict__ b1,
             const float* __restrict__ gn_g,
             const float* __restrict__ gn_b,
             const float* __restrict__ b2)
{
    extern __shared__ __align__(16) char sm[];
    __nv_bfloat16* Hhi = (__nv_bfloat16*)sm;
    __nv_bfloat16* Hlo = (__nv_bfloat16*)(sm + 34816);
    __nv_bfloat16* Whi = (__nv_bfloat16*)(sm + 2 * 34816);
    __nv_bfloat16* Wlo = (__nv_bfloat16*)(sm + 3 * 34816);

    __shared__ float W1s[384], b1s[128], gs[128], bsh[128], b2s[128];
    __shared__ float red[8 * 128];

    const int tid  = threadIdx.x, g = blockIdx.x;
    const int wid  = tid >> 5, lane = tid & 31;

    for (int i = tid; i < 384; i += 256) W1s[i] = W1[i];
    if (tid < 128) {
        b1s[tid] = b1[tid]; gs[tid] = gn_g[tid];
        bsh[tid] = gn_b[tid]; b2s[tid] = b2[tid];
    }
    {
        const uint4* sh = (const uint4*)g_w2hi;
        const uint4* sl = (const uint4*)g_w2lo;
        uint4* dh = (uint4*)Whi;
        uint4* dl = (uint4*)Wlo;
        #pragma unroll
        for (int i = tid; i < 2176; i += 256) { dh[i] = sh[i]; dl[i] = sl[i]; }
    }
    __syncthreads();

    const float* xg = x + (size_t)g * NNODES * 3;
    #pragma unroll
    for (int it = 0; it < 4; it++) {
        const int pair = tid + 256 * it;
        if (pair < NNODES * 8) {
            const int n = pair >> 3, grp = pair & 7;
            const float a0 = xg[n * 3 + 0] * scaler[n * 3 + 0];
            const float a1 = xg[n * 3 + 1] * scaler[n * 3 + 1];
            const float a2 = xg[n * 3 + 2] * scaler[n * 3 + 2];
            float v[16], s = 0.f, ss = 0.f;
            #pragma unroll
            for (int j = 0; j < 16; j++) {
                const int c = grp * 16 + j;
                float h = fmaf(a0, W1s[c],
                          fmaf(a1, W1s[128 + c],
                          fmaf(a2, W1s[256 + c], b1s[c])));
                v[j] = h; s += h; ss += h * h;
            }
            const float mu  = s * 0.0625f;
            const float var = ss * 0.0625f - mu * mu;
            const float inv = rsqrtf(var + EPS);
            const int base = n * WSTRIDE + grp * 16;
            #pragma unroll
            for (int j2 = 0; j2 < 8; j2++) {
                float h0 = (v[2*j2]   - mu) * inv * gs[grp*16 + 2*j2]   + bsh[grp*16 + 2*j2];
                float h1 = (v[2*j2+1] - mu) * inv * gs[grp*16 + 2*j2+1] + bsh[grp*16 + 2*j2+1];
                h0 = h0 > 0.f ? h0 : 0.2f * h0;
                h1 = h1 > 0.f ? h1 : 0.2f * h1;
                const __nv_bfloat16 hi0 = __float2bfloat16(h0);
                const __nv_bfloat16 hi1 = __float2bfloat16(h1);
                __nv_bfloat162 ph; ph.x = hi0; ph.y = hi1;
                __nv_bfloat162 pl;
                pl.x = __float2bfloat16(h0 - __bfloat162float(hi0));
                pl.y = __float2bfloat16(h1 - __bfloat162float(hi1));
                *(__nv_bfloat162*)(Hhi + base + 2*j2) = ph;
                *(__nv_bfloat162*)(Hlo + base + 2*j2) = pl;
            }
        } else if (pair < 128 * 8) {
            const int n = pair >> 3, grp = pair & 7;
            const int base = n * WSTRIDE + grp * 16;
            #pragma unroll
            for (int j2 = 0; j2 < 8; j2++) {
                *(uint32_t*)(Hhi + base + 2*j2) = 0u;
                *(uint32_t*)(Hlo + base + 2*j2) = 0u;
            }
        }
    }
    __syncthreads();

    const uint32_t Hhi_b = smem_u32(Hhi);
    const uint32_t Hlo_b = smem_u32(Hlo);
    const uint32_t Whi_b = smem_u32(Whi);
    const uint32_t Wlo_b = smem_u32(Wlo);

    const int seg = lane >> 3, ris = lane & 7;
    const uint32_t a_off = (uint32_t)(((16 * wid + (seg & 1) * 8 + ris) * WSTRIDE
                                       + (seg >> 1) * 8) * 2);
    const uint32_t b_rel = (uint32_t)((ris * WSTRIDE + (seg & 1) * 8) * 2);

    float acc[16][4];
    #pragma unroll
    for (int j = 0; j < 16; j++)
        #pragma unroll
        for (int q = 0; q < 4; q++) acc[j][q] = 0.f;

    #pragma unroll
    for (int kt = 0; kt < 8; kt++) {
        const int k0 = kt * 16;
        uint32_t ah[4], al[4];
        ldsm_x4(ah, Hhi_b + a_off + k0 * 2);
        ldsm_x4(al, Hlo_b + a_off + k0 * 2);
        #pragma unroll
        for (int j = 0; j < 16; j++) {
            const uint32_t boff = b_rel + (uint32_t)((j * 8 * WSTRIDE + k0) * 2);
            uint32_t bh[2], bl[2];
            ldsm_x2(bh, Whi_b + boff);
            ldsm_x2(bl, Wlo_b + boff);
            mma16816(acc[j], ah, bh);
            mma16816(acc[j], al, bh);
            mma16816(acc[j], ah, bl);
        }
    }

    const int rbase = 16 * wid + (lane >> 2);
    const bool v0 = rbase < NNODES;
    const bool v1 = (rbase + 8) < NNODES;
    #pragma unroll
    for (int j = 0; j < 16; j++) {
        float m0 = fmaxf(v0 ? acc[j][0] : NEGINF, v1 ? acc[j][2] : NEGINF);
        float m1 = fmaxf(v0 ? acc[j][1] : NEGINF, v1 ? acc[j][3] : NEGINF);
        #pragma unroll
        for (int sh = 4; sh < 32; sh <<= 1) {
            m0 = fmaxf(m0, __shfl_xor_sync(0xffffffffu, m0, sh));
            m1 = fmaxf(m1, __shfl_xor_sync(0xffffffffu, m1, sh));
        }
        if (lane < 4) {
            red[wid * 128 + j * 8 + lane * 2]     = m0;
            red[wid * 128 + j * 8 + lane * 2 + 1] = m1;
        }
    }
    __syncthreads();
    if (tid < 128) {
        float m = red[tid];
        #pragma unroll
        for (int w2 = 1; w2 < 8; w2++) m = fmaxf(m, red[w2 * 128 + tid]);
        g_z[(size_t)g * 128 + tid] = m + b2s[tid];
    }
}

// ---------------------------------------------------------------------------
// Kernel 2: p = z @ W3 + b3, fused per-block channel partial stats.
// grid (64, 4). 256 thr.
// ---------------------------------------------------------------------------
__global__ __launch_bounds__(256, 1)
void k_proj(const float* __restrict__ W3, const float* __restrict__ b3)
{
    extern __shared__ float smf[];
    float* zs  = smf;            // 8192
    float* w3s = smf + 8192;     // 16384

    __shared__ float rs[8][128], rq[8][128];

    const int tid  = threadIdx.x;
    const int row0 = blockIdx.x * 64;
    const int col0 = blockIdx.y * 128;

    {
        const float4* zv  = (const float4*)(g_z + (size_t)row0 * 128);
        float4*       zsv = (float4*)zs;
        #pragma unroll
        for (int i = tid; i < 2048; i += 256) zsv[i] = zv[i];

        const float4* W3v  = (const float4*)W3;
        float4*       w3sv = (float4*)w3s;
        #pragma unroll
        for (int i = tid; i < 4096; i += 256) {
            const int k = i >> 5, q = i & 31;
            w3sv[i] = W3v[k * 128 + (col0 >> 2) + q];
        }
    }
    __syncthreads();

    const int tx = tid & 31;
    const int ty = tid >> 5;

    float acc[8][4];
    #pragma unroll
    for (int i = 0; i < 8; i++)
        #pragma unroll
        for (int j = 0; j < 4; j++) acc[i][j] = 0.f;

    #pragma unroll 2
    for (int k = 0; k < 128; k++) {
        float a[8], b[4];
        #pragma unroll
        for (int i = 0; i < 8; i++) a[i] = zs[(ty + 8 * i) * 128 + k];
        #pragma unroll
        for (int j = 0; j < 4; j++) b[j] = w3s[k * 128 + tx + 32 * j];
        #pragma unroll
        for (int i = 0; i < 8; i++)
            #pragma unroll
            for (int j = 0; j < 4; j++)
                acc[i][j] = fmaf(a[i], b[j], acc[i][j]);
    }

    #pragma unroll
    for (int j = 0; j < 4; j++) {
        const int c = col0 + tx + 32 * j;
        const float bc = b3[c];
        float s = 0.f, q = 0.f;
        #pragma unroll
        for (int i = 0; i < 8; i++) {
            const int r = row0 + ty + 8 * i;
            const float p = acc[i][j] + bc;
            g_p[(size_t)r * PDIM + c] = p;
            s += p; q = fmaf(p, p, q);
        }
        rs[ty][tx + 32 * j] = s;
        rq[ty][tx + 32 * j] = q;
    }
    __syncthreads();
    if (tid < 128) {
        float s = 0.f, q = 0.f;
        #pragma unroll
        for (int t = 0; t < 8; t++) { s += rs[t][tid]; q += rq[t][tid]; }
        g_psum[blockIdx.x * PDIM + col0 + tid] = s;
        g_qsum[blockIdx.x * PDIM + col0 + tid] = q;
    }
}

// ---------------------------------------------------------------------------
// Kernel 3: finish batch stats from 64 partials/channel. grid 4 x 128 thr.
// ---------------------------------------------------------------------------
__global__ void k_stats2()
{
    const int c = blockIdx.x * 128 + threadIdx.x;
    float s = 0.f, q = 0.f;
    #pragma unroll 8
    for (int r = 0; r < 64; r++) {
        s += g_psum[r * PDIM + c];
        q += g_qsum[r * PDIM + c];
    }
    const float mean = s * (1.f / NGRAPH);
    const float var  = q * (1.f / NGRAPH) - mean * mean;
    g_mean[c] = mean;
    g_rstd[c] = rsqrtf(var + EPS);
}

// ---------------------------------------------------------------------------
// Kernel 4: out = L2norm( relu(BN(p)) @ W4 + b4 ) via bf16 hi/lo HMMA.
// grid 128 blocks (32 rows each), 256 threads (8 warps x 128-col strips).
// dyn smem: Ahi|Alo [32][KSTR] bf16.
// ---------------------------------------------------------------------------
__global__ __launch_bounds__(256, 1)
void k_out(const float* __restrict__ bn_g, const float* __restrict__ bn_b,
           const float* __restrict__ b4,   float* __restrict__ out)
{
    extern __shared__ __align__(16) char smc[];
    __nv_bfloat16* Ahi = (__nv_bfloat16*)smc;                 // 32*520
    __nv_bfloat16* Alo = (__nv_bfloat16*)(smc + 32 * KSTR * 2);

    __shared__ float red[8][32];
    __shared__ float inv[32];

    const int tid  = threadIdx.x;
    const int wid  = tid >> 5, lane = tid & 31;
    const int row0 = blockIdx.x * 32;

    // ---- stage A = relu(BN(p)) as bf16 hi/lo. 32 rows x 512 cols = 16384
    //      elements = 8192 float2 pairs; 32 iters x 256 threads.
    #pragma unroll
    for (int it = 0; it < 32; it++) {
        const int i = tid + 256 * it;        // 0..8191 (pair index)
        const int r = i >> 8;                // 0..31
        const int c = (i & 255) * 2;         // 0,2,..,510
        const float2 pv = *(const float2*)(g_p + (size_t)(row0 + r) * PDIM + c);
        const float2 mg = *(const float2*)(g_mean + c);
        const float2 rg = *(const float2*)(g_rstd + c);
        const float2 gg = *(const float2*)(bn_g + c);
        const float2 bg = *(const float2*)(bn_b + c);
        float v0 = (pv.x - mg.x) * rg.x * gg.x + bg.x;
        float v1 = (pv.y - mg.y) * rg.y * gg.y + bg.y;
        v0 = v0 > 0.f ? v0 : 0.f;
        v1 = v1 > 0.f ? v1 : 0.f;
        const __nv_bfloat16 h0 = __float2bfloat16(v0);
        const __nv_bfloat16 h1 = __float2bfloat16(v1);
        __nv_bfloat162 ph; ph.x = h0; ph.y = h1;
        __nv_bfloat162 pl;
        pl.x = __float2bfloat16(v0 - __bfloat162float(h0));
        pl.y = __float2bfloat16(v1 - __bfloat162float(h1));
        *(__nv_bfloat162*)(Ahi + r * KSTR + c) = ph;
        *(__nv_bfloat162*)(Alo + r * KSTR + c) = pl;
    }
    __syncthreads();

    const uint32_t Ahi_b = smem_u32(Ahi);
    const uint32_t Alo_b = smem_u32(Alo);
    const int seg = lane >> 3, ris = lane & 7;
    const int nbase = wid * 128;
    const int kfrag = (lane & 3) * 2;

    float acc[2][16][4];
    #pragma unroll
    for (int mt = 0; mt < 2; mt++)
        #pragma unroll
        for (int nt = 0; nt < 16; nt++)
            #pragma unroll
            for (int q = 0; q < 4; q++) acc[mt][nt][q] = 0.f;

    for (int kt = 0; kt < 32; kt++) {
        const int k0 = kt * 16;
        uint32_t ah[2][4], al[2][4];
        #pragma unroll
        for (int mt = 0; mt < 2; mt++) {
            const uint32_t ao = (uint32_t)(((mt * 16 + (seg & 1) * 8 + ris) * KSTR
                                            + (seg >> 1) * 8 + k0) * 2);
            ldsm_x4(ah[mt], Ahi_b + ao);
            ldsm_x4(al[mt], Alo_b + ao);
        }
        #pragma unroll
        for (int nt = 0; nt < 16; nt++) {
            const int nn = nbase + nt * 8 + (lane >> 2);
            const size_t boff = (size_t)nn * PDIM + k0 + kfrag;
            uint32_t bh[2], bl[2];
            bh[0] = *(const uint32_t*)(g_w4hi + boff);
            bh[1] = *(const uint32_t*)(g_w4hi + boff + 8);
            bl[0] = *(const uint32_t*)(g_w4lo + boff);
            bl[1] = *(const uint32_t*)(g_w4lo + boff + 8);
            mma16816(acc[0][nt], ah[0], bh);
            mma16816(acc[1][nt], ah[1], bh);
            mma16816(acc[0][nt], al[0], bh);
            mma16816(acc[1][nt], al[1], bh);
            mma16816(acc[0][nt], ah[0], bl);
            mma16816(acc[1][nt], ah[1], bl);
        }
    }

    // ---- epilogue: + b4, row sum-of-squares, normalize, store
    #pragma unroll
    for (int nt = 0; nt < 16; nt++) {
        const float2 bb = *(const float2*)(b4 + nbase + nt * 8 + (lane & 3) * 2);
        #pragma unroll
        for (int mt = 0; mt < 2; mt++) {
            acc[mt][nt][0] += bb.x; acc[mt][nt][1] += bb.y;
            acc[mt][nt][2] += bb.x; acc[mt][nt][3] += bb.y;
        }
    }

    #pragma unroll
    for (int mt = 0; mt < 2; mt++) {
        const int r0 = mt * 16 + (lane >> 2);
        float s0 = 0.f, s1 = 0.f;
        #pragma unroll
        for (int nt = 0; nt < 16; nt++) {
            s0 = fmaf(acc[mt][nt][0], acc[mt][nt][0],
                 fmaf(acc[mt][nt][1], acc[mt][nt][1], s0));
            s1 = fmaf(acc[mt][nt][2], acc[mt][nt][2],
                 fmaf(acc[mt][nt][3], acc[mt][nt][3], s1));
        }
        s0 += __shfl_xor_sync(0xffffffffu, s0, 1);
        s0 += __shfl_xor_sync(0xffffffffu, s0, 2);
        s1 += __shfl_xor_sync(0xffffffffu, s1, 1);
        s1 += __shfl_xor_sync(0xffffffffu, s1, 2);
        if ((lane & 3) == 0) {
            red[wid][r0]     = s0;
            red[wid][r0 + 8] = s1;
        }
    }
    __syncthreads();
    if (tid < 32) {
        float s = 0.f;
        #pragma unroll
        for (int w = 0; w < 8; w++) s += red[w][tid];
        inv[tid] = 1.f / fmaxf(sqrtf(s), 1e-12f);
    }
    __syncthreads();

    #pragma unroll
    for (int mt = 0; mt < 2; mt++) {
        const int r0 = mt * 16 + (lane >> 2);
        const float iv0 = inv[r0], iv1 = inv[r0 + 8];
        #pragma unroll
        for (int nt = 0; nt < 16; nt++) {
            const int c = nbase + nt * 8 + (lane & 3) * 2;
            float2 o0, o1;
            o0.x = acc[mt][nt][0] * iv0; o0.y = acc[mt][nt][1] * iv0;
            o1.x = acc[mt][nt][2] * iv1; o1.y = acc[mt][nt][3] * iv1;
            *(float2*)(out + (size_t)(row0 + r0) * EMB + c)     = o0;
            *(float2*)(out + (size_t)(row0 + r0 + 8) * EMB + c) = o1;
        }
    }
}

// ---------------------------------------------------------------------------
extern "C" void kernel_launch(void* const* d_in, const int* in_sizes, int n_in,
                              void* d_out, int out_size)
{
    const float* x      = (const float*)d_in[0];
    const float* scaler = (const float*)d_in[1];
    const float* W1     = (const float*)d_in[2];
    const float* b1     = (const float*)d_in[3];
    const float* gn_g   = (const float*)d_in[4];
    const float* gn_b   = (const float*)d_in[5];
    const float* W2     = (const float*)d_in[6];
    const float* b2     = (const float*)d_in[7];
    const float* W3     = (const float*)d_in[8];
    const float* b3     = (const float*)d_in[9];
    const float* bn_g   = (const float*)d_in[10];
    const float* bn_b   = (const float*)d_in[11];
    const float* W4     = (const float*)d_in[12];
    const float* b4     = (const float*)d_in[13];
    float* out = (float*)d_out;

    const int smem1 = 4 * 34816;              // 139264
    const int smem2 = (8192 + 16384) * 4;     // 98304
    const int smem4 = 2 * 32 * KSTR * 2;      // 66560
    cudaFuncSetAttribute(k_nodes, cudaFuncAttributeMaxDynamicSharedMemorySize, smem1);
    cudaFuncSetAttribute(k_proj,  cudaFuncAttributeMaxDynamicSharedMemorySize, smem2);
    cudaFuncSetAttribute(k_out,   cudaFuncAttributeMaxDynamicSharedMemorySize, smem4);

    k_prep<<<64, 256>>>(W2);
    k_prep4<<<2048, 256>>>(W4);
    k_nodes<<<NGRAPH, 256, smem1>>>(x, scaler, W1, b1, gn_g, gn_b, b2);
    k_proj<<<dim3(64, 4), 256, smem2>>>(W3, b3);
    k_stats2<<<4, 128>>>();
    k_out<<<128, 256, smem4>>>(bn_g, bn_b, b4, out);
}

// round 7
// speedup vs baseline: 3.3887x; 1.1062x over previous
#include <cuda_runtime.h>
#include <cuda_bf16.h>
#include <math.h>
#include <cstdint>

#define NGRAPH 4096
#define NNODES 113
#define HID    128
#define PDIM   512
#define EMB    1024
#define EPS    1e-5f
#define NEGINF -3.402823466e+38f
#define WSTRIDE 136   // padded bf16 row stride (elements) for MMA smem tiles
#define KSTR    520   // padded bf16 row stride for k_out A tiles
#define ROWS_PB 256   // node rows per k_nodes block
#define NBLK    1808  // 462848 / 256

// ---------------------------------------------------------------------------
// Scratch (no cudaMalloc allowed)
// ---------------------------------------------------------------------------
__device__ float g_zA[NGRAPH * HID];       // pooled partial (start block)
__device__ float g_zB[NGRAPH * HID];       // pooled partial (continuation)
__device__ float g_p[NGRAPH * PDIM];
__device__ float g_mean[PDIM];
__device__ float g_rstd[PDIM];
__device__ float g_psum[64 * PDIM];
__device__ float g_qsum[64 * PDIM];
__device__ __align__(16) __nv_bfloat16 g_w2hi[128 * WSTRIDE];
__device__ __align__(16) __nv_bfloat16 g_w2lo[128 * WSTRIDE];
__device__ __align__(16) __nv_bfloat16 g_w4hi[EMB * PDIM];
__device__ __align__(16) __nv_bfloat16 g_w4lo[EMB * PDIM];

// ---------------------------------------------------------------------------
// mma.sync helpers (plain sm_103-safe)
// ---------------------------------------------------------------------------
__device__ __forceinline__ uint32_t smem_u32(const void* p) {
    uint32_t a;
    asm("{ .reg .u64 t; cvta.to.shared.u64 t, %1; cvt.u32.u64 %0, t; }"
        : "=r"(a) : "l"(p));
    return a;
}
__device__ __forceinline__ void ldsm_x4(uint32_t* r, uint32_t addr) {
    asm volatile("ldmatrix.sync.aligned.m8n8.x4.shared.b16 {%0,%1,%2,%3}, [%4];"
        : "=r"(r[0]), "=r"(r[1]), "=r"(r[2]), "=r"(r[3]) : "r"(addr));
}
__device__ __forceinline__ void mma16816(float* d, const uint32_t* a, const uint32_t* b) {
    asm volatile(
        "mma.sync.aligned.m16n8k16.row.col.f32.bf16.bf16.f32 "
        "{%0,%1,%2,%3}, {%4,%5,%6,%7}, {%8,%9}, {%0,%1,%2,%3};"
        : "+f"(d[0]), "+f"(d[1]), "+f"(d[2]), "+f"(d[3])
        : "r"(a[0]), "r"(a[1]), "r"(a[2]), "r"(a[3]), "r"(b[0]), "r"(b[1]));
}

// ---------------------------------------------------------------------------
// Prep: weight splits
// ---------------------------------------------------------------------------
__global__ void k_prep(const float* __restrict__ W2)
{
    const int idx = blockIdx.x * blockDim.x + threadIdx.x;
    if (idx >= 16384) return;
    const int n = idx >> 7, k = idx & 127;
    const float v = W2[k * 128 + n];
    const __nv_bfloat16 hi = __float2bfloat16(v);
    g_w2hi[n * WSTRIDE + k] = hi;
    g_w2lo[n * WSTRIDE + k] = __float2bfloat16(v - __bfloat162float(hi));
}

__global__ void k_prep4(const float* __restrict__ W4)
{
    const int idx = blockIdx.x * blockDim.x + threadIdx.x;   // 524288
    const int n = idx >> 9, k = idx & 511;
    const float v = W4[(size_t)k * EMB + n];
    const __nv_bfloat16 hi = __float2bfloat16(v);
    g_w4hi[(size_t)n * PDIM + k] = hi;
    g_w4lo[(size_t)n * PDIM + k] = __float2bfloat16(v - __bfloat162float(hi));
}

// ---------------------------------------------------------------------------
// Kernel 1: 256-row node tile (graph-agnostic GEMM) + segmented max pool.
// grid = 1808, 256 threads (8 warps, 32 rows/warp = 2 m-tiles).
// dyn smem: Hhi | Hlo | Whi | Wlo  (69632 + 69632 + 34816 + 34816 = 208896)
// ---------------------------------------------------------------------------
__global__ __launch_bounds__(256, 1)
void k_nodes(const float* __restrict__ x,
             const float* __restrict__ scaler,
             const float* __restrict__ W1,
             const float* __restrict__ b1,
             const float* __restrict__ gn_g,
             const float* __restrict__ gn_b)
{
    extern __shared__ __align__(16) char sm[];
    __nv_bfloat16* Hhi = (__nv_bfloat16*)sm;                       // 256*136
    __nv_bfloat16* Hlo = (__nv_bfloat16*)(sm + 69632);
    __nv_bfloat16* Whi = (__nv_bfloat16*)(sm + 139264);
    __nv_bfloat16* Wlo = (__nv_bfloat16*)(sm + 174080);
    float* red = (float*)sm;   // reused AFTER MMA: [4 seg][8 warps][128]

    __shared__ float W1s[384], b1s[128], gs[128], bsh[128];

    const int tid  = threadIdx.x;
    const int wid  = tid >> 5, lane = tid & 31;
    const int R0   = blockIdx.x * ROWS_PB;

    for (int i = tid; i < 384; i += 256) W1s[i] = W1[i];
    if (tid < 128) {
        b1s[tid] = b1[tid]; gs[tid] = gn_g[tid]; bsh[tid] = gn_b[tid];
    }
    {
        const uint4* sh = (const uint4*)g_w2hi;
        const uint4* sl = (const uint4*)g_w2lo;
        uint4* dh = (uint4*)Whi;
        uint4* dl = (uint4*)Wlo;
        #pragma unroll
        for (int i = tid; i < 2176; i += 256) { dh[i] = sh[i]; dl[i] = sl[i]; }
    }
    __syncthreads();

    // ---- H rows (all 256 real): GN(x*scaler @ W1 + b1) -> LeakyReLU -> hi/lo
    #pragma unroll
    for (int it = 0; it < 8; it++) {
        const int pair = tid + 256 * it;            // 0..2047
        const int n = pair >> 3, grp = pair & 7;
        const int gr  = R0 + n;                     // global node row
        const int roi = gr % NNODES;
        const float a0 = x[gr * 3 + 0] * scaler[roi * 3 + 0];
        const float a1 = x[gr * 3 + 1] * scaler[roi * 3 + 1];
        const float a2 = x[gr * 3 + 2] * scaler[roi * 3 + 2];
        float v[16], s = 0.f, ss = 0.f;
        #pragma unroll
        for (int j = 0; j < 16; j++) {
            const int c = grp * 16 + j;
            float h = fmaf(a0, W1s[c],
                      fmaf(a1, W1s[128 + c],
                      fmaf(a2, W1s[256 + c], b1s[c])));
            v[j] = h; s += h; ss += h * h;
        }
        const float mu  = s * 0.0625f;
        const float var = ss * 0.0625f - mu * mu;
        const float inv = rsqrtf(var + EPS);
        const int base = n * WSTRIDE + grp * 16;
        #pragma unroll
        for (int j2 = 0; j2 < 8; j2++) {
            const int c0 = grp * 16 + 2 * j2;
            float h0 = (v[2*j2]   - mu) * inv * gs[c0]     + bsh[c0];
            float h1 = (v[2*j2+1] - mu) * inv * gs[c0 + 1] + bsh[c0 + 1];
            h0 = h0 > 0.f ? h0 : 0.2f * h0;
            h1 = h1 > 0.f ? h1 : 0.2f * h1;
            const __nv_bfloat16 hi0 = __float2bfloat16(h0);
            const __nv_bfloat16 hi1 = __float2bfloat16(h1);
            __nv_bfloat162 ph; ph.x = hi0; ph.y = hi1;
            __nv_bfloat162 pl;
            pl.x = __float2bfloat16(h0 - __bfloat162float(hi0));
            pl.y = __float2bfloat16(h1 - __bfloat162float(hi1));
            *(__nv_bfloat162*)(Hhi + base + 2*j2) = ph;
            *(__nv_bfloat162*)(Hlo + base + 2*j2) = pl;
        }
    }
    __syncthreads();

    // ---- HMMA mainloop: warp strip = 32 rows (2 m-tiles), 128 cols
    const uint32_t Hhi_b = smem_u32(Hhi);
    const uint32_t Hlo_b = smem_u32(Hlo);
    const uint32_t Whi_b = smem_u32(Whi);
    const uint32_t Wlo_b = smem_u32(Wlo);

    const int lgrp = lane >> 3, ris = lane & 7;
    // A x4 address (per m-tile): rows r0 + (lgrp&1)*8 + ris, col (lgrp>>1)*8
    const uint32_t aoff0 = (uint32_t)(((wid * 32 +      (lgrp & 1) * 8 + ris) * WSTRIDE
                                       + (lgrp >> 1) * 8) * 2);
    const uint32_t aoff1 = aoff0 + (uint32_t)(16 * WSTRIDE * 2);
    // B x4 address (per j-pair): rows (j + (lgrp>>1))*8 + ris, col (lgrp&1)*8
    const uint32_t brel  = (uint32_t)((((lgrp >> 1) * 8 + ris) * WSTRIDE
                                       + (lgrp & 1) * 8) * 2);

    float acc[2][16][4];
    #pragma unroll
    for (int mt = 0; mt < 2; mt++)
        #pragma unroll
        for (int j = 0; j < 16; j++)
            #pragma unroll
            for (int q = 0; q < 4; q++) acc[mt][j][q] = 0.f;

    #pragma unroll
    for (int kt = 0; kt < 8; kt++) {
        const uint32_t kb = (uint32_t)(kt * 16 * 2);
        uint32_t ah0[4], al0[4], ah1[4], al1[4];
        ldsm_x4(ah0, Hhi_b + aoff0 + kb);
        ldsm_x4(al0, Hlo_b + aoff0 + kb);
        ldsm_x4(ah1, Hhi_b + aoff1 + kb);
        ldsm_x4(al1, Hlo_b + aoff1 + kb);
        #pragma unroll
        for (int jp = 0; jp < 8; jp++) {
            const uint32_t bo = brel + (uint32_t)(jp * 16 * WSTRIDE * 2) + kb;
            uint32_t bh[4], bl[4];
            ldsm_x4(bh, Whi_b + bo);
            ldsm_x4(bl, Wlo_b + bo);
            // tile j = 2*jp uses {bh[0],bh[1]}, tile 2*jp+1 uses {bh[2],bh[3]}
            mma16816(acc[0][2*jp],   ah0, bh);
            mma16816(acc[1][2*jp],   ah1, bh);
            mma16816(acc[0][2*jp+1], ah0, bh + 2);
            mma16816(acc[1][2*jp+1], ah1, bh + 2);
            mma16816(acc[0][2*jp],   al0, bh);
            mma16816(acc[1][2*jp],   al1, bh);
            mma16816(acc[0][2*jp+1], al0, bh + 2);
            mma16816(acc[1][2*jp+1], al1, bh + 2);
            mma16816(acc[0][2*jp],   ah0, bl);
            mma16816(acc[1][2*jp],   ah1, bl);
            mma16816(acc[0][2*jp+1], ah0, bl + 2);
            mma16816(acc[1][2*jp+1], ah1, bl + 2);
        }
    }
    __syncthreads();   // all warps done reading H smem; red aliases it now

    // ---- segmented max pool: block intersects graphs g0..g0+nseg-1 (<=4)
    const int g0 = R0 / NNODES;
    const int g3 = (R0 + ROWS_PB - 1) / NNODES;
    const int nseg = g3 - g0 + 1;

    // thread's 4 candidate local rows (block-local)
    const int rl0 = wid * 32 + (lane >> 2);
    #pragma unroll
    for (int s = 0; s < 4; s++) {
        if (s >= nseg) break;
        const int gg = g0 + s;
        const int lo = max(gg * NNODES - R0, 0);
        const int hi = min(gg * NNODES + NNODES - R0, ROWS_PB);
        const bool c0 = (rl0      >= lo) && (rl0      < hi);
        const bool c1 = (rl0 + 8  >= lo) && (rl0 + 8  < hi);
        const bool c2 = (rl0 + 16 >= lo) && (rl0 + 16 < hi);
        const bool c3 = (rl0 + 24 >= lo) && (rl0 + 24 < hi);
        #pragma unroll
        for (int j = 0; j < 16; j++) {
            float m0 = NEGINF, m1 = NEGINF;
            if (c0) { m0 = acc[0][j][0]; m1 = acc[0][j][1]; }
            if (c1) { m0 = fmaxf(m0, acc[0][j][2]); m1 = fmaxf(m1, acc[0][j][3]); }
            if (c2) { m0 = fmaxf(m0, acc[1][j][0]); m1 = fmaxf(m1, acc[1][j][1]); }
            if (c3) { m0 = fmaxf(m0, acc[1][j][2]); m1 = fmaxf(m1, acc[1][j][3]); }
            #pragma unroll
            for (int sh = 4; sh < 32; sh <<= 1) {
                m0 = fmaxf(m0, __shfl_xor_sync(0xffffffffu, m0, sh));
                m1 = fmaxf(m1, __shfl_xor_sync(0xffffffffu, m1, sh));
            }
            if (lane < 4) {
                red[(s * 8 + wid) * 128 + j * 8 + lane * 2]     = m0;
                red[(s * 8 + wid) * 128 + j * 8 + lane * 2 + 1] = m1;
            }
        }
    }
    __syncthreads();

    if (tid < 128) {
        #pragma unroll
        for (int s = 0; s < 4; s++) {
            if (s >= nseg) break;
            const int gg = g0 + s;
            float m = red[(s * 8) * 128 + tid];
            #pragma unroll
            for (int w = 1; w < 8; w++)
                m = fmaxf(m, red[(s * 8 + w) * 128 + tid]);
            const int gstart = gg * NNODES;
            if (gstart >= R0) {
                g_zA[(size_t)gg * 128 + tid] = m;
                if (gstart + NNODES <= R0 + ROWS_PB)        // fully contained
                    g_zB[(size_t)gg * 128 + tid] = NEGINF;
            } else {
                g_zB[(size_t)gg * 128 + tid] = m;
            }
        }
    }
}

// ---------------------------------------------------------------------------
// Kernel 2: p = z @ W3 + b3 (z = max(zA,zB)+b2), fused channel partial stats.
// grid (64, 4). 256 thr.
// ---------------------------------------------------------------------------
__global__ __launch_bounds__(256, 1)
void k_proj(const float* __restrict__ W3, const float* __restrict__ b3,
            const float* __restrict__ b2)
{
    extern __shared__ float smf[];
    float* zs  = smf;            // 8192
    float* w3s = smf + 8192;     // 16384

    __shared__ float rs[8][128], rq[8][128];
    __shared__ float b2s[128];

    const int tid  = threadIdx.x;
    const int row0 = blockIdx.x * 64;
    const int col0 = blockIdx.y * 128;

    if (tid < 128) b2s[tid] = b2[tid];
    {
        const float4* zav = (const float4*)(g_zA + (size_t)row0 * 128);
        const float4* zbv = (const float4*)(g_zB + (size_t)row0 * 128);
        float4*       zsv = (float4*)zs;
        #pragma unroll
        for (int i = tid; i < 2048; i += 256) {
            const float4 a = zav[i], b = zbv[i];
            const int c4 = (i & 31) * 4;
            float4 z;
            z.x = fmaxf(a.x, b.x) + b2[c4 + 0];
            z.y = fmaxf(a.y, b.y) + b2[c4 + 1];
            z.z = fmaxf(a.z, b.z) + b2[c4 + 2];
            z.w = fmaxf(a.w, b.w) + b2[c4 + 3];
            zsv[i] = z;
        }
        const float4* W3v  = (const float4*)W3;
        float4*       w3sv = (float4*)w3s;
        #pragma unroll
        for (int i = tid; i < 4096; i += 256) {
            const int k = i >> 5, q = i & 31;
            w3sv[i] = W3v[k * 128 + (col0 >> 2) + q];
        }
    }
    __syncthreads();

    const int tx = tid & 31;
    const int ty = tid >> 5;

    float acc[8][4];
    #pragma unroll
    for (int i = 0; i < 8; i++)
        #pragma unroll
        for (int j = 0; j < 4; j++) acc[i][j] = 0.f;

    #pragma unroll 2
    for (int k = 0; k < 128; k++) {
        float a[8], b[4];
        #pragma unroll
        for (int i = 0; i < 8; i++) a[i] = zs[(ty + 8 * i) * 128 + k];
        #pragma unroll
        for (int j = 0; j < 4; j++) b[j] = w3s[k * 128 + tx + 32 * j];
        #pragma unroll
        for (int i = 0; i < 8; i++)
            #pragma unroll
            for (int j = 0; j < 4; j++)
                acc[i][j] = fmaf(a[i], b[j], acc[i][j]);
    }

    #pragma unroll
    for (int j = 0; j < 4; j++) {
        const int c = col0 + tx + 32 * j;
        const float bc = b3[c];
        float s = 0.f, q = 0.f;
        #pragma unroll
        for (int i = 0; i < 8; i++) {
            const int r = row0 + ty + 8 * i;
            const float p = acc[i][j] + bc;
            g_p[(size_t)r * PDIM + c] = p;
            s += p; q = fmaf(p, p, q);
        }
        rs[ty][tx + 32 * j] = s;
        rq[ty][tx + 32 * j] = q;
    }
    __syncthreads();
    if (tid < 128) {
        float s = 0.f, q = 0.f;
        #pragma unroll
        for (int t = 0; t < 8; t++) { s += rs[t][tid]; q += rq[t][tid]; }
        g_psum[blockIdx.x * PDIM + col0 + tid] = s;
        g_qsum[blockIdx.x * PDIM + col0 + tid] = q;
    }
}

// ---------------------------------------------------------------------------
// Kernel 3: finish batch stats. grid 4 x 128 thr.
// ---------------------------------------------------------------------------
__global__ void k_stats2()
{
    const int c = blockIdx.x * 128 + threadIdx.x;
    float s = 0.f, q = 0.f;
    #pragma unroll 8
    for (int r = 0; r < 64; r++) {
        s += g_psum[r * PDIM + c];
        q += g_qsum[r * PDIM + c];
    }
    const float mean = s * (1.f / NGRAPH);
    const float var  = q * (1.f / NGRAPH) - mean * mean;
    g_mean[c] = mean;
    g_rstd[c] = rsqrtf(var + EPS);
}

// ---------------------------------------------------------------------------
// Kernel 4: out = L2norm( relu(BN(p)) @ W4 + b4 ) via bf16 hi/lo HMMA.
// grid 128 blocks (32 rows each), 256 threads.
// ---------------------------------------------------------------------------
__global__ __launch_bounds__(256, 1)
void k_out(const float* __restrict__ bn_g, const float* __restrict__ bn_b,
           const float* __restrict__ b4,   float* __restrict__ out)
{
    extern __shared__ __align__(16) char smc[];
    __nv_bfloat16* Ahi = (__nv_bfloat16*)smc;                 // 32*520
    __nv_bfloat16* Alo = (__nv_bfloat16*)(smc + 32 * KSTR * 2);

    __shared__ float red[8][32];
    __shared__ float inv[32];

    const int tid  = threadIdx.x;
    const int wid  = tid >> 5, lane = tid & 31;
    const int row0 = blockIdx.x * 32;

    #pragma unroll
    for (int it = 0; it < 32; it++) {
        const int i = tid + 256 * it;        // pair index 0..8191
        const int r = i >> 8;
        const int c = (i & 255) * 2;
        const float2 pv = *(const float2*)(g_p + (size_t)(row0 + r) * PDIM + c);
        const float2 mg = *(const float2*)(g_mean + c);
        const float2 rg = *(const float2*)(g_rstd + c);
        const float2 gg = *(const float2*)(bn_g + c);
        const float2 bg = *(const float2*)(bn_b + c);
        float v0 = (pv.x - mg.x) * rg.x * gg.x + bg.x;
        float v1 = (pv.y - mg.y) * rg.y * gg.y + bg.y;
        v0 = v0 > 0.f ? v0 : 0.f;
        v1 = v1 > 0.f ? v1 : 0.f;
        const __nv_bfloat16 h0 = __float2bfloat16(v0);
        const __nv_bfloat16 h1 = __float2bfloat16(v1);
        __nv_bfloat162 ph; ph.x = h0; ph.y = h1;
        __nv_bfloat162 pl;
        pl.x = __float2bfloat16(v0 - __bfloat162float(h0));
        pl.y = __float2bfloat16(v1 - __bfloat162float(h1));
        *(__nv_bfloat162*)(Ahi + r * KSTR + c) = ph;
        *(__nv_bfloat162*)(Alo + r * KSTR + c) = pl;
    }
    __syncthreads();

    const uint32_t Ahi_b = smem_u32(Ahi);
    const uint32_t Alo_b = smem_u32(Alo);
    const int seg = lane >> 3, ris = lane & 7;
    const int nbase = wid * 128;
    const int kfrag = (lane & 3) * 2;

    float acc[2][16][4];
    #pragma unroll
    for (int mt = 0; mt < 2; mt++)
        #pragma unroll
        for (int nt = 0; nt < 16; nt++)
            #pragma unroll
            for (int q = 0; q < 4; q++) acc[mt][nt][q] = 0.f;

    for (int kt = 0; kt < 32; kt++) {
        const int k0 = kt * 16;
        uint32_t ah[2][4], al[2][4];
        #pragma unroll
        for (int mt = 0; mt < 2; mt++) {
            const uint32_t ao = (uint32_t)(((mt * 16 + (seg & 1) * 8 + ris) * KSTR
                                            + (seg >> 1) * 8 + k0) * 2);
            ldsm_x4(ah[mt], Ahi_b + ao);
            ldsm_x4(al[mt], Alo_b + ao);
        }
        #pragma unroll
        for (int nt = 0; nt < 16; nt++) {
            const int nn = nbase + nt * 8 + (lane >> 2);
            const size_t boff = (size_t)nn * PDIM + k0 + kfrag;
            uint32_t bh[2], bl[2];
            bh[0] = *(const uint32_t*)(g_w4hi + boff);
            bh[1] = *(const uint32_t*)(g_w4hi + boff + 8);
            bl[0] = *(const uint32_t*)(g_w4lo + boff);
            bl[1] = *(const uint32_t*)(g_w4lo + boff + 8);
            mma16816(acc[0][nt], ah[0], bh);
            mma16816(acc[1][nt], ah[1], bh);
            mma16816(acc[0][nt], al[0], bh);
            mma16816(acc[1][nt], al[1], bh);
            mma16816(acc[0][nt], ah[0], bl);
            mma16816(acc[1][nt], ah[1], bl);
        }
    }

    #pragma unroll
    for (int nt = 0; nt < 16; nt++) {
        const float2 bb = *(const float2*)(b4 + nbase + nt * 8 + (lane & 3) * 2);
        #pragma unroll
        for (int mt = 0; mt < 2; mt++) {
            acc[mt][nt][0] += bb.x; acc[mt][nt][1] += bb.y;
            acc[mt][nt][2] += bb.x; acc[mt][nt][3] += bb.y;
        }
    }

    #pragma unroll
    for (int mt = 0; mt < 2; mt++) {
        const int r0 = mt * 16 + (lane >> 2);
        float s0 = 0.f, s1 = 0.f;
        #pragma unroll
        for (int nt = 0; nt < 16; nt++) {
            s0 = fmaf(acc[mt][nt][0], acc[mt][nt][0],
                 fmaf(acc[mt][nt][1], acc[mt][nt][1], s0));
            s1 = fmaf(acc[mt][nt][2], acc[mt][nt][2],
                 fmaf(acc[mt][nt][3], acc[mt][nt][3], s1));
        }
        s0 += __shfl_xor_sync(0xffffffffu, s0, 1);
        s0 += __shfl_xor_sync(0xffffffffu, s0, 2);
        s1 += __shfl_xor_sync(0xffffffffu, s1, 1);
        s1 += __shfl_xor_sync(0xffffffffu, s1, 2);
        if ((lane & 3) == 0) {
            red[wid][r0]     = s0;
            red[wid][r0 + 8] = s1;
        }
    }
    __syncthreads();
    if (tid < 32) {
        float s = 0.f;
        #pragma unroll
        for (int w = 0; w < 8; w++) s += red[w][tid];
        inv[tid] = 1.f / fmaxf(sqrtf(s), 1e-12f);
    }
    __syncthreads();

    #pragma unroll
    for (int mt = 0; mt < 2; mt++) {
        const int r0 = mt * 16 + (lane >> 2);
        const float iv0 = inv[r0], iv1 = inv[r0 + 8];
        #pragma unroll
        for (int nt = 0; nt < 16; nt++) {
            const int c = nbase + nt * 8 + (lane & 3) * 2;
            float2 o0, o1;
            o0.x = acc[mt][nt][0] * iv0; o0.y = acc[mt][nt][1] * iv0;
            o1.x = acc[mt][nt][2] * iv1; o1.y = acc[mt][nt][3] * iv1;
            *(float2*)(out + (size_t)(row0 + r0) * EMB + c)     = o0;
            *(float2*)(out + (size_t)(row0 + r0 + 8) * EMB + c) = o1;
        }
    }
}

// ---------------------------------------------------------------------------
extern "C" void kernel_launch(void* const* d_in, const int* in_sizes, int n_in,
                              void* d_out, int out_size)
{
    const float* x      = (const float*)d_in[0];
    const float* scaler = (const float*)d_in[1];
    const float* W1     = (const float*)d_in[2];
    const float* b1     = (const float*)d_in[3];
    const float* gn_g   = (const float*)d_in[4];
    const float* gn_b   = (const float*)d_in[5];
    const float* W2     = (const float*)d_in[6];
    const float* b2     = (const float*)d_in[7];
    const float* W3     = (const float*)d_in[8];
    const float* b3     = (const float*)d_in[9];
    const float* bn_g   = (const float*)d_in[10];
    const float* bn_b   = (const float*)d_in[11];
    const float* W4     = (const float*)d_in[12];
    const float* b4     = (const float*)d_in[13];
    float* out = (float*)d_out;

    const int smem1 = 208896;                 // Hhi|Hlo|Whi|Wlo
    const int smem2 = (8192 + 16384) * 4;     // 98304
    const int smem4 = 2 * 32 * KSTR * 2;      // 66560
    cudaFuncSetAttribute(k_nodes, cudaFuncAttributeMaxDynamicSharedMemorySize, smem1);
    cudaFuncSetAttribute(k_proj,  cudaFuncAttributeMaxDynamicSharedMemorySize, smem2);
    cudaFuncSetAttribute(k_out,   cudaFuncAttributeMaxDynamicSharedMemorySize, smem4);

    k_prep<<<64, 256>>>(W2);
    k_prep4<<<2048, 256>>>(W4);
    k_nodes<<<NBLK, 256, smem1>>>(x, scaler, W1, b1, gn_g, gn_b);
    k_proj<<<dim3(64, 4), 256, smem2>>>(W3, b3, b2);
    k_stats2<<<4, 128>>>();
    k_out<<<128, 256, smem4>>>(bn_g, bn_b, b4, out);
}

// round 9
// speedup vs baseline: 3.5162x; 1.0376x over previous
#include <cuda_runtime.h>
#include <cuda_bf16.h>
#include <math.h>
#include <cstdint>

#define NGRAPH 4096
#define NNODES 113
#define HID    128
#define PDIM   512
#define EMB    1024
#define EPS    1e-5f
#define NEGINF -3.402823466e+38f
#define WSTRIDE 136   // padded bf16 row stride (elements) for MMA smem tiles
#define KSTR    520   // padded bf16 row stride for k_out A tiles
#define ROWS_PB 256   // node rows per k_nodes block
#define NBLK    1808  // 462848 / 256

// ---------------------------------------------------------------------------
// Scratch (no cudaMalloc allowed)
// ---------------------------------------------------------------------------
__device__ float g_zA[NGRAPH * HID];       // pooled partial (start block)
__device__ float g_zB[NGRAPH * HID];       // pooled partial (continuation)
__device__ float g_p[NGRAPH * PDIM];
__device__ float g_mean[PDIM];
__device__ float g_rstd[PDIM];
__device__ float g_psum[64 * PDIM];
__device__ float g_qsum[64 * PDIM];
__device__ float g_rsq[4 * NGRAPH];        // per-colblock row sumsq partials
__device__ __align__(16) __nv_bfloat16 g_w2hi[128 * WSTRIDE];
__device__ __align__(16) __nv_bfloat16 g_w2lo[128 * WSTRIDE];
__device__ __align__(16) __nv_bfloat16 g_w4hi[EMB * PDIM];
__device__ __align__(16) __nv_bfloat16 g_w4lo[EMB * PDIM];

// ---------------------------------------------------------------------------
// mma.sync helpers (plain sm_103-safe)
// ---------------------------------------------------------------------------
__device__ __forceinline__ uint32_t smem_u32(const void* p) {
    uint32_t a;
    asm("{ .reg .u64 t; cvta.to.shared.u64 t, %1; cvt.u32.u64 %0, t; }"
        : "=r"(a) : "l"(p));
    return a;
}
__device__ __forceinline__ void ldsm_x4(uint32_t* r, uint32_t addr) {
    asm volatile("ldmatrix.sync.aligned.m8n8.x4.shared.b16 {%0,%1,%2,%3}, [%4];"
        : "=r"(r[0]), "=r"(r[1]), "=r"(r[2]), "=r"(r[3]) : "r"(addr));
}
__device__ __forceinline__ void mma16816(float* d, const uint32_t* a, const uint32_t* b) {
    asm volatile(
        "mma.sync.aligned.m16n8k16.row.col.f32.bf16.bf16.f32 "
        "{%0,%1,%2,%3}, {%4,%5,%6,%7}, {%8,%9}, {%0,%1,%2,%3};"
        : "+f"(d[0]), "+f"(d[1]), "+f"(d[2]), "+f"(d[3])
        : "r"(a[0]), "r"(a[1]), "r"(a[2]), "r"(a[3]), "r"(b[0]), "r"(b[1]));
}

// ---------------------------------------------------------------------------
// Prep: weight splits
// ---------------------------------------------------------------------------
__global__ void k_prep(const float* __restrict__ W2)
{
    const int idx = blockIdx.x * blockDim.x + threadIdx.x;
    if (idx >= 16384) return;
    const int n = idx >> 7, k = idx & 127;
    const float v = W2[k * 128 + n];
    const __nv_bfloat16 hi = __float2bfloat16(v);
    g_w2hi[n * WSTRIDE + k] = hi;
    g_w2lo[n * WSTRIDE + k] = __float2bfloat16(v - __bfloat162float(hi));
}

__global__ void k_prep4(const float* __restrict__ W4)
{
    const int idx = blockIdx.x * blockDim.x + threadIdx.x;   // 524288
    const int n = idx >> 9, k = idx & 511;
    const float v = W4[(size_t)k * EMB + n];
    const __nv_bfloat16 hi = __float2bfloat16(v);
    g_w4hi[(size_t)n * PDIM + k] = hi;
    g_w4lo[(size_t)n * PDIM + k] = __float2bfloat16(v - __bfloat162float(hi));
}

// ---------------------------------------------------------------------------
// Kernel 1: 256-row node tile (graph-agnostic GEMM) + segmented max pool.
// ---------------------------------------------------------------------------
__global__ __launch_bounds__(256, 1)
void k_nodes(const float* __restrict__ x,
             const float* __restrict__ scaler,
             const float* __restrict__ W1,
             const float* __restrict__ b1,
             const float* __restrict__ gn_g,
             const float* __restrict__ gn_b)
{
    extern __shared__ __align__(16) char sm[];
    __nv_bfloat16* Hhi = (__nv_bfloat16*)sm;                       // 256*136
    __nv_bfloat16* Hlo = (__nv_bfloat16*)(sm + 69632);
    __nv_bfloat16* Whi = (__nv_bfloat16*)(sm + 139264);
    __nv_bfloat16* Wlo = (__nv_bfloat16*)(sm + 174080);
    float* red = (float*)sm;   // reused AFTER MMA: [4 seg][8 warps][128]

    __shared__ float W1s[384], b1s[128], gs[128], bsh[128];

    const int tid  = threadIdx.x;
    const int wid  = tid >> 5, lane = tid & 31;
    const int R0   = blockIdx.x * ROWS_PB;

    for (int i = tid; i < 384; i += 256) W1s[i] = W1[i];
    if (tid < 128) {
        b1s[tid] = b1[tid]; gs[tid] = gn_g[tid]; bsh[tid] = gn_b[tid];
    }
    {
        const uint4* sh = (const uint4*)g_w2hi;
        const uint4* sl = (const uint4*)g_w2lo;
        uint4* dh = (uint4*)Whi;
        uint4* dl = (uint4*)Wlo;
        #pragma unroll
        for (int i = tid; i < 2176; i += 256) { dh[i] = sh[i]; dl[i] = sl[i]; }
    }
    __syncthreads();

    #pragma unroll
    for (int it = 0; it < 8; it++) {
        const int pair = tid + 256 * it;            // 0..2047
        const int n = pair >> 3, grp = pair & 7;
        const int gr  = R0 + n;
        const int roi = gr % NNODES;
        const float a0 = x[gr * 3 + 0] * scaler[roi * 3 + 0];
        const float a1 = x[gr * 3 + 1] * scaler[roi * 3 + 1];
        const float a2 = x[gr * 3 + 2] * scaler[roi * 3 + 2];
        float v[16], s = 0.f, ss = 0.f;
        #pragma unroll
        for (int j = 0; j < 16; j++) {
            const int c = grp * 16 + j;
            float h = fmaf(a0, W1s[c],
                      fmaf(a1, W1s[128 + c],
                      fmaf(a2, W1s[256 + c], b1s[c])));
            v[j] = h; s += h; ss += h * h;
        }
        const float mu  = s * 0.0625f;
        const float var = ss * 0.0625f - mu * mu;
        const float inv = rsqrtf(var + EPS);
        const int base = n * WSTRIDE + grp * 16;
        #pragma unroll
        for (int j2 = 0; j2 < 8; j2++) {
            const int c0 = grp * 16 + 2 * j2;
            float h0 = (v[2*j2]   - mu) * inv * gs[c0]     + bsh[c0];
            float h1 = (v[2*j2+1] - mu) * inv * gs[c0 + 1] + bsh[c0 + 1];
            h0 = h0 > 0.f ? h0 : 0.2f * h0;
            h1 = h1 > 0.f ? h1 : 0.2f * h1;
            const __nv_bfloat16 hi0 = __float2bfloat16(h0);
            const __nv_bfloat16 hi1 = __float2bfloat16(h1);
            __nv_bfloat162 ph; ph.x = hi0; ph.y = hi1;
            __nv_bfloat162 pl;
            pl.x = __float2bfloat16(h0 - __bfloat162float(hi0));
            pl.y = __float2bfloat16(h1 - __bfloat162float(hi1));
            *(__nv_bfloat162*)(Hhi + base + 2*j2) = ph;
            *(__nv_bfloat162*)(Hlo + base + 2*j2) = pl;
        }
    }
    __syncthreads();

    const uint32_t Hhi_b = smem_u32(Hhi);
    const uint32_t Hlo_b = smem_u32(Hlo);
    const uint32_t Whi_b = smem_u32(Whi);
    const uint32_t Wlo_b = smem_u32(Wlo);

    const int lgrp = lane >> 3, ris = lane & 7;
    const uint32_t aoff0 = (uint32_t)(((wid * 32 +      (lgrp & 1) * 8 + ris) * WSTRIDE
                                       + (lgrp >> 1) * 8) * 2);
    const uint32_t aoff1 = aoff0 + (uint32_t)(16 * WSTRIDE * 2);
    const uint32_t brel  = (uint32_t)((((lgrp >> 1) * 8 + ris) * WSTRIDE
                                       + (lgrp & 1) * 8) * 2);

    float acc[2][16][4];
    #pragma unroll
    for (int mt = 0; mt < 2; mt++)
        #pragma unroll
        for (int j = 0; j < 16; j++)
            #pragma unroll
            for (int q = 0; q < 4; q++) acc[mt][j][q] = 0.f;

    #pragma unroll
    for (int kt = 0; kt < 8; kt++) {
        const uint32_t kb = (uint32_t)(kt * 16 * 2);
        uint32_t ah0[4], al0[4], ah1[4], al1[4];
        ldsm_x4(ah0, Hhi_b + aoff0 + kb);
        ldsm_x4(al0, Hlo_b + aoff0 + kb);
        ldsm_x4(ah1, Hhi_b + aoff1 + kb);
        ldsm_x4(al1, Hlo_b + aoff1 + kb);
        #pragma unroll
        for (int jp = 0; jp < 8; jp++) {
            const uint32_t bo = brel + (uint32_t)(jp * 16 * WSTRIDE * 2) + kb;
            uint32_t bh[4], bl[4];
            ldsm_x4(bh, Whi_b + bo);
            ldsm_x4(bl, Wlo_b + bo);
            mma16816(acc[0][2*jp],   ah0, bh);
            mma16816(acc[1][2*jp],   ah1, bh);
            mma16816(acc[0][2*jp+1], ah0, bh + 2);
            mma16816(acc[1][2*jp+1], ah1, bh + 2);
            mma16816(acc[0][2*jp],   al0, bh);
            mma16816(acc[1][2*jp],   al1, bh);
            mma16816(acc[0][2*jp+1], al0, bh + 2);
            mma16816(acc[1][2*jp+1], al1, bh + 2);
            mma16816(acc[0][2*jp],   ah0, bl);
            mma16816(acc[1][2*jp],   ah1, bl);
            mma16816(acc[0][2*jp+1], ah0, bl + 2);
            mma16816(acc[1][2*jp+1], ah1, bl + 2);
        }
    }
    __syncthreads();

    const int g0 = R0 / NNODES;
    const int g3 = (R0 + ROWS_PB - 1) / NNODES;
    const int nseg = g3 - g0 + 1;

    const int rl0 = wid * 32 + (lane >> 2);
    #pragma unroll
    for (int s = 0; s < 4; s++) {
        if (s >= nseg) break;
        const int gg = g0 + s;
        const int lo = max(gg * NNODES - R0, 0);
        const int hi = min(gg * NNODES + NNODES - R0, ROWS_PB);
        const bool c0 = (rl0      >= lo) && (rl0      < hi);
        const bool c1 = (rl0 + 8  >= lo) && (rl0 + 8  < hi);
        const bool c2 = (rl0 + 16 >= lo) && (rl0 + 16 < hi);
        const bool c3 = (rl0 + 24 >= lo) && (rl0 + 24 < hi);
        #pragma unroll
        for (int j = 0; j < 16; j++) {
            float m0 = NEGINF, m1 = NEGINF;
            if (c0) { m0 = acc[0][j][0]; m1 = acc[0][j][1]; }
            if (c1) { m0 = fmaxf(m0, acc[0][j][2]); m1 = fmaxf(m1, acc[0][j][3]); }
            if (c2) { m0 = fmaxf(m0, acc[1][j][0]); m1 = fmaxf(m1, acc[1][j][1]); }
            if (c3) { m0 = fmaxf(m0, acc[1][j][2]); m1 = fmaxf(m1, acc[1][j][3]); }
            #pragma unroll
            for (int sh = 4; sh < 32; sh <<= 1) {
                m0 = fmaxf(m0, __shfl_xor_sync(0xffffffffu, m0, sh));
                m1 = fmaxf(m1, __shfl_xor_sync(0xffffffffu, m1, sh));
            }
            if (lane < 4) {
                red[(s * 8 + wid) * 128 + j * 8 + lane * 2]     = m0;
                red[(s * 8 + wid) * 128 + j * 8 + lane * 2 + 1] = m1;
            }
        }
    }
    __syncthreads();

    if (tid < 128) {
        #pragma unroll
        for (int s = 0; s < 4; s++) {
            if (s >= nseg) break;
            const int gg = g0 + s;
            float m = red[(s * 8) * 128 + tid];
            #pragma unroll
            for (int w = 1; w < 8; w++)
                m = fmaxf(m, red[(s * 8 + w) * 128 + tid]);
            const int gstart = gg * NNODES;
            if (gstart >= R0) {
                g_zA[(size_t)gg * 128 + tid] = m;
                if (gstart + NNODES <= R0 + ROWS_PB)
                    g_zB[(size_t)gg * 128 + tid] = NEGINF;
            } else {
                g_zB[(size_t)gg * 128 + tid] = m;
            }
        }
    }
}

// ---------------------------------------------------------------------------
// Kernel 2: p = z @ W3 + b3 (z = max(zA,zB)+b2), fused channel partial stats.
// ---------------------------------------------------------------------------
__global__ __launch_bounds__(256, 1)
void k_proj(const float* __restrict__ W3, const float* __restrict__ b3,
            const float* __restrict__ b2)
{
    extern __shared__ float smf[];
    float* zs  = smf;            // 8192
    float* w3s = smf + 8192;     // 16384

    __shared__ float rs[8][128], rq[8][128];

    const int tid  = threadIdx.x;
    const int row0 = blockIdx.x * 64;
    const int col0 = blockIdx.y * 128;

    {
        const float4* zav = (const float4*)(g_zA + (size_t)row0 * 128);
        const float4* zbv = (const float4*)(g_zB + (size_t)row0 * 128);
        float4*       zsv = (float4*)zs;
        #pragma unroll
        for (int i = tid; i < 2048; i += 256) {
            const float4 a = zav[i], b = zbv[i];
            const int c4 = (i & 31) * 4;
            float4 z;
            z.x = fmaxf(a.x, b.x) + b2[c4 + 0];
            z.y = fmaxf(a.y, b.y) + b2[c4 + 1];
            z.z = fmaxf(a.z, b.z) + b2[c4 + 2];
            z.w = fmaxf(a.w, b.w) + b2[c4 + 3];
            zsv[i] = z;
        }
        const float4* W3v  = (const float4*)W3;
        float4*       w3sv = (float4*)w3s;
        #pragma unroll
        for (int i = tid; i < 4096; i += 256) {
            const int k = i >> 5, q = i & 31;
            w3sv[i] = W3v[k * 128 + (col0 >> 2) + q];
        }
    }
    __syncthreads();

    const int tx = tid & 31;
    const int ty = tid >> 5;

    float acc[8][4];
    #pragma unroll
    for (int i = 0; i < 8; i++)
        #pragma unroll
        for (int j = 0; j < 4; j++) acc[i][j] = 0.f;

    #pragma unroll 2
    for (int k = 0; k < 128; k++) {
        float a[8], b[4];
        #pragma unroll
        for (int i = 0; i < 8; i++) a[i] = zs[(ty + 8 * i) * 128 + k];
        #pragma unroll
        for (int j = 0; j < 4; j++) b[j] = w3s[k * 128 + tx + 32 * j];
        #pragma unroll
        for (int i = 0; i < 8; i++)
            #pragma unroll
            for (int j = 0; j < 4; j++)
                acc[i][j] = fmaf(a[i], b[j], acc[i][j]);
    }

    #pragma unroll
    for (int j = 0; j < 4; j++) {
        const int c = col0 + tx + 32 * j;
        const float bc = b3[c];
        float s = 0.f, q = 0.f;
        #pragma unroll
        for (int i = 0; i < 8; i++) {
            const int r = row0 + ty + 8 * i;
            const float p = acc[i][j] + bc;
            g_p[(size_t)r * PDIM + c] = p;
            s += p; q = fmaf(p, p, q);
        }
        rs[ty][tx + 32 * j] = s;
        rq[ty][tx + 32 * j] = q;
    }
    __syncthreads();
    if (tid < 128) {
        float s = 0.f, q = 0.f;
        #pragma unroll
        for (int t = 0; t < 8; t++) { s += rs[t][tid]; q += rq[t][tid]; }
        g_psum[blockIdx.x * PDIM + col0 + tid] = s;
        g_qsum[blockIdx.x * PDIM + col0 + tid] = q;
    }
}

// ---------------------------------------------------------------------------
// Kernel 3: finish batch stats. grid 4 x 128 thr.
// ---------------------------------------------------------------------------
__global__ void k_stats2()
{
    const int c = blockIdx.x * 128 + threadIdx.x;
    float s = 0.f, q = 0.f;
    #pragma unroll 8
    for (int r = 0; r < 64; r++) {
        s += g_psum[r * PDIM + c];
        q += g_qsum[r * PDIM + c];
    }
    const float mean = s * (1.f / NGRAPH);
    const float var  = q * (1.f / NGRAPH) - mean * mean;
    g_mean[c] = mean;
    g_rstd[c] = rsqrtf(var + EPS);
}

// ---------------------------------------------------------------------------
// Kernel 4: unnormalized out = relu(BN(p)) @ W4 + b4, + row sumsq partials.
// grid (64 rowblocks, 4 colblocks) = 256 blocks, 256 threads.
// dyn smem: Ahi|Alo [64][KSTR] bf16 = 133120 B.
// ---------------------------------------------------------------------------
__global__ __launch_bounds__(256, 1)
void k_out(const float* __restrict__ bn_g, const float* __restrict__ bn_b,
           const float* __restrict__ b4,   float* __restrict__ out)
{
    extern __shared__ __align__(16) char smc[];
    __nv_bfloat16* Ahi = (__nv_bfloat16*)smc;                 // 64*520
    __nv_bfloat16* Alo = (__nv_bfloat16*)(smc + 64 * KSTR * 2);

    __shared__ float red[8][64];

    const int tid  = threadIdx.x;
    const int wid  = tid >> 5, lane = tid & 31;
    const int row0 = blockIdx.x * 64;
    const int col0 = blockIdx.y * 256;

    // ---- stage A = relu(BN(p)): thread owns fixed column pair c = 2*tid
    {
        const int c = tid * 2;
        const float2 mg = *(const float2*)(g_mean + c);
        const float2 rg = *(const float2*)(g_rstd + c);
        const float2 gg = *(const float2*)(bn_g + c);
        const float2 bg = *(const float2*)(bn_b + c);
        const float s0 = rg.x * gg.x, s1 = rg.y * gg.y;
        const float o0 = bg.x - mg.x * s0, o1 = bg.y - mg.y * s1;
        #pragma unroll 4
        for (int r = 0; r < 64; r++) {
            const float2 pv = *(const float2*)(g_p + (size_t)(row0 + r) * PDIM + c);
            float v0 = fmaf(pv.x, s0, o0);
            float v1 = fmaf(pv.y, s1, o1);
            v0 = v0 > 0.f ? v0 : 0.f;
            v1 = v1 > 0.f ? v1 : 0.f;
            const __nv_bfloat16 h0 = __float2bfloat16(v0);
            const __nv_bfloat16 h1 = __float2bfloat16(v1);
            __nv_bfloat162 ph; ph.x = h0; ph.y = h1;
            __nv_bfloat162 pl;
            pl.x = __float2bfloat16(v0 - __bfloat162float(h0));
            pl.y = __float2bfloat16(v1 - __bfloat162float(h1));
            *(__nv_bfloat162*)(Ahi + r * KSTR + c) = ph;
            *(__nv_bfloat162*)(Alo + r * KSTR + c) = pl;
        }
    }
    __syncthreads();

    const uint32_t Ahi_b = smem_u32(Ahi);
    const uint32_t Alo_b = smem_u32(Alo);
    const int seg = lane >> 3, ris = lane & 7;
    const int kfrag = (lane & 3) * 2;
    const int nwarp = col0 + wid * 32;

    float acc[4][4][4];
    #pragma unroll
    for (int mt = 0; mt < 4; mt++)
        #pragma unroll
        for (int nt = 0; nt < 4; nt++)
            #pragma unroll
            for (int q = 0; q < 4; q++) acc[mt][nt][q] = 0.f;

    for (int kt = 0; kt < 32; kt++) {
        const int k0 = kt * 16;
        uint32_t ah[4][4], al[4][4];
        #pragma unroll
        for (int mt = 0; mt < 4; mt++) {
            const uint32_t ao = (uint32_t)(((mt * 16 + (seg & 1) * 8 + ris) * KSTR
                                            + (seg >> 1) * 8 + k0) * 2);
            ldsm_x4(ah[mt], Ahi_b + ao);
            ldsm_x4(al[mt], Alo_b + ao);
        }
        #pragma unroll
        for (int nt = 0; nt < 4; nt++) {
            const int nn = nwarp + nt * 8 + (lane >> 2);
            const size_t boff = (size_t)nn * PDIM + k0 + kfrag;
            uint32_t bh[2], bl[2];
            bh[0] = *(const uint32_t*)(g_w4hi + boff);
            bh[1] = *(const uint32_t*)(g_w4hi + boff + 8);
            bl[0] = *(const uint32_t*)(g_w4lo + boff);
            bl[1] = *(const uint32_t*)(g_w4lo + boff + 8);
            #pragma unroll
            for (int mt = 0; mt < 4; mt++) {
                mma16816(acc[mt][nt], ah[mt], bh);
                mma16816(acc[mt][nt], al[mt], bh);
                mma16816(acc[mt][nt], ah[mt], bl);
            }
        }
    }

    // ---- epilogue: + b4, per-row sumsq partial, store unnormalized
    #pragma unroll
    for (int nt = 0; nt < 4; nt++) {
        const float2 bb = *(const float2*)(b4 + nwarp + nt * 8 + (lane & 3) * 2);
        #pragma unroll
        for (int mt = 0; mt < 4; mt++) {
            acc[mt][nt][0] += bb.x; acc[mt][nt][1] += bb.y;
            acc[mt][nt][2] += bb.x; acc[mt][nt][3] += bb.y;
        }
    }

    #pragma unroll
    for (int mt = 0; mt < 4; mt++) {
        float s0 = 0.f, s1 = 0.f;
        #pragma unroll
        for (int nt = 0; nt < 4; nt++) {
            s0 = fmaf(acc[mt][nt][0], acc[mt][nt][0],
                 fmaf(acc[mt][nt][1], acc[mt][nt][1], s0));
            s1 = fmaf(acc[mt][nt][2], acc[mt][nt][2],
                 fmaf(acc[mt][nt][3], acc[mt][nt][3], s1));
        }
        s0 += __shfl_xor_sync(0xffffffffu, s0, 1);
        s0 += __shfl_xor_sync(0xffffffffu, s0, 2);
        s1 += __shfl_xor_sync(0xffffffffu, s1, 1);
        s1 += __shfl_xor_sync(0xffffffffu, s1, 2);
        if ((lane & 3) == 0) {
            red[wid][mt * 16 + (lane >> 2)]     = s0;
            red[wid][mt * 16 + 8 + (lane >> 2)] = s1;
        }
    }
    __syncthreads();
    if (tid < 64) {
        float s = 0.f;
        #pragma unroll
        for (int w = 0; w < 8; w++) s += red[w][tid];
        g_rsq[(size_t)blockIdx.y * NGRAPH + row0 + tid] = s;
    }

    #pragma unroll
    for (int mt = 0; mt < 4; mt++) {
        const int r0 = row0 + mt * 16 + (lane >> 2);
        #pragma unroll
        for (int nt = 0; nt < 4; nt++) {
            const int c = nwarp + nt * 8 + (lane & 3) * 2;
            float2 o0, o1;
            o0.x = acc[mt][nt][0]; o0.y = acc[mt][nt][1];
            o1.x = acc[mt][nt][2]; o1.y = acc[mt][nt][3];
            *(float2*)(out + (size_t)r0 * EMB + c)       = o0;
            *(float2*)(out + (size_t)(r0 + 8) * EMB + c) = o1;
        }
    }
}

// ---------------------------------------------------------------------------
// Kernel 5: row L2 normalize in place. grid NGRAPH, 256 thr (float4 each).
// ---------------------------------------------------------------------------
__global__ __launch_bounds__(256, 1)
void k_norm(float* __restrict__ out)
{
    __shared__ float iv;
    const int r = blockIdx.x;
    if (threadIdx.x == 0) {
        const float s = g_rsq[r] + g_rsq[NGRAPH + r]
                      + g_rsq[2 * NGRAPH + r] + g_rsq[3 * NGRAPH + r];
        iv = 1.f / fmaxf(sqrtf(s), 1e-12f);
    }
    __syncthreads();
    float4* o = (float4*)(out + (size_t)r * EMB);
    float4 v = o[threadIdx.x];
    v.x *= iv; v.y *= iv; v.z *= iv; v.w *= iv;
    o[threadIdx.x] = v;
}

// ---------------------------------------------------------------------------
extern "C" void kernel_launch(void* const* d_in, const int* in_sizes, int n_in,
                              void* d_out, int out_size)
{
    const float* x      = (const float*)d_in[0];
    const float* scaler = (const float*)d_in[1];
    const float* W1     = (const float*)d_in[2];
    const float* b1     = (const float*)d_in[3];
    const float* gn_g   = (const float*)d_in[4];
    const float* gn_b   = (const float*)d_in[5];
    const float* W2     = (const float*)d_in[6];
    const float* b2     = (const float*)d_in[7];
    const float* W3     = (const float*)d_in[8];
    const float* b3     = (const float*)d_in[9];
    const float* bn_g   = (const float*)d_in[10];
    const float* bn_b   = (const float*)d_in[11];
    const float* W4     = (const float*)d_in[12];
    const float* b4     = (const float*)d_in[13];
    float* out = (float*)d_out;

    const int smem1 = 208896;                 // Hhi|Hlo|Whi|Wlo
    const int smem2 = (8192 + 16384) * 4;     // 98304
    const int smem4 = 2 * 64 * KSTR * 2;      // 133120
    cudaFuncSetAttribute(k_nodes, cudaFuncAttributeMaxDynamicSharedMemorySize, smem1);
    cudaFuncSetAttribute(k_proj,  cudaFuncAttributeMaxDynamicSharedMemorySize, smem2);
    cudaFuncSetAttribute(k_out,   cudaFuncAttributeMaxDynamicSharedMemorySize, smem4);

    k_prep<<<64, 256>>>(W2);
    k_prep4<<<2048, 256>>>(W4);
    k_nodes<<<NBLK, 256, smem1>>>(x, scaler, W1, b1, gn_g, gn_b);
    k_proj<<<dim3(64, 4), 256, smem2>>>(W3, b3, b2);
    k_stats2<<<4, 128>>>();
    k_out<<<dim3(64, 4), 256, smem4>>>(bn_g, bn_b, b4, out);
    k_norm<<<NGRAPH, 256>>>(out);
}